// round 7
// baseline (speedup 1.0000x reference)
#include <cuda_runtime.h>
#include <cstdint>

#define N_NODES 100000
#define N_EDGES 1600000
#define DIM     128
#define T_NODES 4096
#define P_PAIRS 131072
#define HP      256
#define DOUT    128
#define ZDIM    64

// ---------------- scratch (static device globals; no allocation) ----------------
__device__ int   g_cnt[N_NODES];
__device__ int   g_rowptr[N_NODES + 1];
__device__ int   g_cursor[N_NODES];
__device__ int   g_col[N_EDGES];
__device__ float g_invdeg[N_NODES];
__device__ unsigned char g_flag[N_NODES];
__device__ unsigned char g_tflag[N_NODES];
__device__ float g_pe[N_NODES * 4];
__device__ float g_zb[HP];
__device__ float g_wf[DIM * HP];                    // W2c @ Wp1[0:128]
__device__ float g_buf1[(size_t)N_NODES * DIM];
__device__ float g_buf2[(size_t)N_NODES * DIM];
__device__ float g_buf3[(size_t)N_NODES * DIM];
__device__ float g_buf4[(size_t)N_NODES * DIM];
__device__ float g_tbuf[(size_t)T_NODES * DIM];
__device__ float g_hidden[(size_t)P_PAIRS * HP];

// ---------------- tf32 / mma helpers ----------------
__device__ __forceinline__ unsigned f2tf(float f) {
    unsigned u;
    asm("cvt.rna.tf32.f32 %0, %1;" : "=r"(u) : "f"(f));
    return u;
}
__device__ __forceinline__ void mma8(float* c, const unsigned* a, const unsigned* b) {
    asm volatile(
        "mma.sync.aligned.m16n8k8.row.col.f32.tf32.tf32.f32 "
        "{%0,%1,%2,%3},{%4,%5,%6,%7},{%8,%9},{%0,%1,%2,%3};"
        : "+f"(c[0]), "+f"(c[1]), "+f"(c[2]), "+f"(c[3])
        : "r"(a[0]), "r"(a[1]), "r"(a[2]), "r"(a[3]), "r"(b[0]), "r"(b[1]));
}

// ---------------- CSR build ----------------
__global__ void k_zero_cnt() {
    int i = blockIdx.x * blockDim.x + threadIdx.x;
    if (i < N_NODES) { g_cnt[i] = 0; g_flag[i] = 0; g_tflag[i] = 0; }
}

__global__ void k_count(const int* __restrict__ dst) {
    int e = blockIdx.x * blockDim.x + threadIdx.x;
    if (e < N_EDGES) atomicAdd(&g_cnt[dst[e]], 1);
}

__global__ void k_scan() {
    __shared__ int sums[1024];
    const int CH = (N_NODES + 1024) / 1024;
    int t = threadIdx.x;
    int base = t * CH;
    int s = 0;
    for (int i = 0; i < CH; i++) {
        int idx = base + i;
        if (idx < N_NODES) s += g_cnt[idx];
    }
    sums[t] = s;
    __syncthreads();
    for (int off = 1; off < 1024; off <<= 1) {
        int v = (t >= off) ? sums[t - off] : 0;
        __syncthreads();
        sums[t] += v;
        __syncthreads();
    }
    int run = sums[t] - s;
    for (int i = 0; i < CH; i++) {
        int idx = base + i;
        if (idx <= N_NODES) g_rowptr[idx] = run;
        if (idx < N_NODES) run += g_cnt[idx];
    }
}

__global__ void k_prep() {
    int i = blockIdx.x * blockDim.x + threadIdx.x;
    if (i < N_NODES) {
        g_cursor[i] = g_rowptr[i];
        int c = g_cnt[i];
        g_invdeg[i] = 1.0f / (float)(c > 0 ? c : 1);
    }
}

__global__ void k_fill(const int* __restrict__ src, const int* __restrict__ dst) {
    int e = blockIdx.x * blockDim.x + threadIdx.x;
    if (e < N_EDGES) {
        int pos = atomicAdd(&g_cursor[dst[e]], 1);
        g_col[pos] = src[e];
    }
}

__global__ void k_flag(const int* __restrict__ pair_s, const float* __restrict__ mask) {
    int i = blockIdx.x * blockDim.x + threadIdx.x;
    if (i < P_PAIRS && mask[i] != 0.f) g_flag[pair_s[i]] = 1;
}

// mark in-neighbors of target nodes (rows of h_t actually consumed by agg_target)
__global__ void k_tflag(const int* __restrict__ tgt) {
    int b = blockIdx.x * blockDim.x + threadIdx.x;
    if (b >= T_NODES) return;
    int n = tgt[b];
    int e = g_rowptr[n + 1];
    for (int i = g_rowptr[n]; i < e; i++) g_tflag[g_col[i]] = 1;
}

// ---------------- tiny precomputes ----------------
__global__ void k_pe(const float* __restrict__ pos_enc, const float* __restrict__ Wpe) {
    int n = blockIdx.x * blockDim.x + threadIdx.x;
    if (n >= N_NODES) return;
    float4 p = *(const float4*)&pos_enc[n * 4];
#pragma unroll
    for (int i = 0; i < 4; i++) {
        g_pe[n * 4 + i] = p.x * Wpe[i * 4 + 0] + p.y * Wpe[i * 4 + 1] +
                          p.z * Wpe[i * 4 + 2] + p.w * Wpe[i * 4 + 3];
    }
}

__global__ void k_zb(const float* __restrict__ z, const float* __restrict__ Wp1,
                     const float* __restrict__ bp1) {
    int j = threadIdx.x;
    float acc = bp1[j];
    for (int i = 0; i < ZDIM; i++) acc = fmaf(z[i], Wp1[(128 + i) * HP + j], acc);
    g_zb[j] = acc;
}

__global__ void k_wf(const float* __restrict__ W2c, const float* __restrict__ Wp1) {
    int i = blockIdx.x;
    int j = threadIdx.x;
    float acc = 0.f;
    for (int d = 0; d < DIM; d++) acc = fmaf(W2c[i * DIM + d], Wp1[d * HP + j], acc);
    g_wf[i * HP + j] = acc;
}

// ---------------- tf32 GEMM: C[M,128] = (relu?)(A[M,128] @ B[128,128]) -------------
// 128x128 block, 256 threads (8 warps 4m x 2n). Whole B resident transposed [n][k],
// staged+converted once. A register-prefetched across 4 chunks of k=32.
// Fragments via scalar LDS (R4-proven addressing; 4*gid+tig bank pattern = no conflicts).
#define AS_STR 36
#define BK_STR 132
#define GEMM_SMEM ((128 * AS_STR + 128 * BK_STR) * 4)

__global__ void __launch_bounds__(256, 2)
k_gemm_tf32(const float* __restrict__ A, const float* __restrict__ B,
            float* __restrict__ C, int M, int relu) {
    extern __shared__ unsigned dynsmem[];
    unsigned* As  = dynsmem;                 // [row][k] stride 36 (k within chunk)
    unsigned* Bst = dynsmem + 128 * AS_STR;  // [n][k]  stride 132 (full k)
    int tid = threadIdx.x;
    int lane = tid & 31, wid = tid >> 5;
    int wm = wid & 3, wn = wid >> 2;         // warp tile: rows wm*32, cols wn*64
    int gid = lane >> 2, tig = lane & 3;
    int m0 = blockIdx.x * 128;

    // ---- stage whole B transposed + tf32 (once) ----
#pragma unroll
    for (int it = 0; it < 16; it++) {
        int idx = tid + it * 256;          // 0..4095
        int n = idx & 127, kg = idx >> 7;  // kg = k-group of 4 (0..31)
        uint4 u;
        u.x = f2tf(B[(size_t)(kg * 4 + 0) * 128 + n]);
        u.y = f2tf(B[(size_t)(kg * 4 + 1) * 128 + n]);
        u.z = f2tf(B[(size_t)(kg * 4 + 2) * 128 + n]);
        u.w = f2tf(B[(size_t)(kg * 4 + 3) * 128 + n]);
        *(uint4*)&Bst[n * BK_STR + kg * 4] = u;
    }

    // ---- A prefetch (chunk 0) ----
    int ar = tid >> 1, acb = (tid & 1) * 16;
    bool rok = (m0 + ar) < M;
    const float* aptr = &A[(size_t)(m0 + ar) * 128 + acb];
    float4 ra[4];
#pragma unroll
    for (int q = 0; q < 4; q++)
        ra[q] = rok ? *(const float4*)(aptr + q * 4) : make_float4(0.f, 0.f, 0.f, 0.f);

    float c[2][8][4];
#pragma unroll
    for (int mt = 0; mt < 2; mt++)
#pragma unroll
        for (int nt = 0; nt < 8; nt++)
#pragma unroll
            for (int q = 0; q < 4; q++) c[mt][nt][q] = 0.f;

    for (int ch = 0; ch < 4; ch++) {
        // store prefetched A chunk to smem (tf32)
#pragma unroll
        for (int q = 0; q < 4; q++) {
            uint4 u = make_uint4(f2tf(ra[q].x), f2tf(ra[q].y), f2tf(ra[q].z), f2tf(ra[q].w));
            *(uint4*)&As[ar * AS_STR + acb + q * 4] = u;
        }
        __syncthreads();
        if (ch < 3) {
            const float* ap = aptr + (ch + 1) * 32;
#pragma unroll
            for (int q = 0; q < 4; q++)
                ra[q] = rok ? *(const float4*)(ap + q * 4)
                            : make_float4(0.f, 0.f, 0.f, 0.f);
        }
        int kB = ch * 32;  // base into Bst's full-k axis
#pragma unroll
        for (int ks = 0; ks < 4; ks++) {
            int kb = ks * 8;
            unsigned a[2][4], b[8][2];
#pragma unroll
            for (int mt = 0; mt < 2; mt++) {
                int r = wm * 32 + mt * 16 + gid;
                a[mt][0] = As[r * AS_STR + kb + tig];
                a[mt][1] = As[(r + 8) * AS_STR + kb + tig];
                a[mt][2] = As[r * AS_STR + kb + tig + 4];
                a[mt][3] = As[(r + 8) * AS_STR + kb + tig + 4];
            }
#pragma unroll
            for (int nt = 0; nt < 8; nt++) {
                int bc = wn * 64 + nt * 8 + gid;
                b[nt][0] = Bst[bc * BK_STR + kB + kb + tig];
                b[nt][1] = Bst[bc * BK_STR + kB + kb + tig + 4];
            }
#pragma unroll
            for (int mt = 0; mt < 2; mt++)
#pragma unroll
                for (int nt = 0; nt < 8; nt++) mma8(c[mt][nt], a[mt], b[nt]);
        }
        __syncthreads();
    }

#pragma unroll
    for (int mt = 0; mt < 2; mt++) {
        int r = m0 + wm * 32 + mt * 16 + gid;
#pragma unroll
        for (int nt = 0; nt < 8; nt++) {
            int col = wn * 64 + nt * 8 + 2 * tig;
            float2 v0 = make_float2(c[mt][nt][0], c[mt][nt][1]);
            float2 v1 = make_float2(c[mt][nt][2], c[mt][nt][3]);
            if (relu) {
                v0.x = fmaxf(v0.x, 0.f); v0.y = fmaxf(v0.y, 0.f);
                v1.x = fmaxf(v1.x, 0.f); v1.y = fmaxf(v1.y, 0.f);
            }
            if (r < M)     *(float2*)&C[(size_t)r * 128 + col] = v0;
            if (r + 8 < M) *(float2*)&C[(size_t)(r + 8) * 128 + col] = v1;
        }
    }
}

// ---------------- fused dual aggregation (first layer of both GCNs) ----------------
// hc[n] = relu(agg(bc)[n]) for all n;  ht[n] = relu(agg(bt)[n]) only where tflag.
__global__ void k_agg_dual(const float* __restrict__ bt, const float* __restrict__ bc,
                           float* __restrict__ ht, float* __restrict__ hc) {
    int n = blockIdx.x * 8 + (threadIdx.x >> 5);
    if (n >= N_NODES) return;
    int lane = threadIdx.x & 31;
    int s = g_rowptr[n], e = g_rowptr[n + 1];
    bool dot = g_tflag[n] != 0;
    float4 z = make_float4(0.f, 0.f, 0.f, 0.f);
    float4 ac0 = z, ac1 = z, at0 = z, at1 = z;
    int i = s;
    for (; i + 2 <= e; i += 2) {
        int c0 = g_col[i], c1 = g_col[i + 1];
        float4 v0 = *(const float4*)&bc[(size_t)c0 * 128 + lane * 4];
        float4 v1 = *(const float4*)&bc[(size_t)c1 * 128 + lane * 4];
        ac0.x += v0.x; ac0.y += v0.y; ac0.z += v0.z; ac0.w += v0.w;
        ac1.x += v1.x; ac1.y += v1.y; ac1.z += v1.z; ac1.w += v1.w;
        if (dot) {
            float4 w0 = *(const float4*)&bt[(size_t)c0 * 128 + lane * 4];
            float4 w1 = *(const float4*)&bt[(size_t)c1 * 128 + lane * 4];
            at0.x += w0.x; at0.y += w0.y; at0.z += w0.z; at0.w += w0.w;
            at1.x += w1.x; at1.y += w1.y; at1.z += w1.z; at1.w += w1.w;
        }
    }
    if (i < e) {
        int c0 = g_col[i];
        float4 v0 = *(const float4*)&bc[(size_t)c0 * 128 + lane * 4];
        ac0.x += v0.x; ac0.y += v0.y; ac0.z += v0.z; ac0.w += v0.w;
        if (dot) {
            float4 w0 = *(const float4*)&bt[(size_t)c0 * 128 + lane * 4];
            at0.x += w0.x; at0.y += w0.y; at0.z += w0.z; at0.w += w0.w;
        }
    }
    float inv = g_invdeg[n];
    float4 rc = make_float4(fmaxf((ac0.x + ac1.x) * inv, 0.f),
                            fmaxf((ac0.y + ac1.y) * inv, 0.f),
                            fmaxf((ac0.z + ac1.z) * inv, 0.f),
                            fmaxf((ac0.w + ac1.w) * inv, 0.f));
    *(float4*)&hc[(size_t)n * 128 + lane * 4] = rc;
    if (dot) {
        float4 rt = make_float4(fmaxf((at0.x + at1.x) * inv, 0.f),
                                fmaxf((at0.y + at1.y) * inv, 0.f),
                                fmaxf((at0.z + at1.z) * inv, 0.f),
                                fmaxf((at0.w + at1.w) * inv, 0.f));
        *(float4*)&ht[(size_t)n * 128 + lane * 4] = rt;
    }
}

// ---------------- single-matrix aggregations ----------------
__device__ __forceinline__ void agg_node(const float* __restrict__ in, int n, int lane,
                                         float4& r) {
    int s = g_rowptr[n], e = g_rowptr[n + 1];
    float4 a0 = make_float4(0.f, 0.f, 0.f, 0.f), a1 = a0, a2 = a0, a3 = a0;
    int i = s;
    for (; i + 4 <= e; i += 4) {
        int c0 = g_col[i], c1 = g_col[i + 1], c2 = g_col[i + 2], c3 = g_col[i + 3];
        float4 v0 = *(const float4*)&in[(size_t)c0 * 128 + lane * 4];
        float4 v1 = *(const float4*)&in[(size_t)c1 * 128 + lane * 4];
        float4 v2 = *(const float4*)&in[(size_t)c2 * 128 + lane * 4];
        float4 v3 = *(const float4*)&in[(size_t)c3 * 128 + lane * 4];
        a0.x += v0.x; a0.y += v0.y; a0.z += v0.z; a0.w += v0.w;
        a1.x += v1.x; a1.y += v1.y; a1.z += v1.z; a1.w += v1.w;
        a2.x += v2.x; a2.y += v2.y; a2.z += v2.z; a2.w += v2.w;
        a3.x += v3.x; a3.y += v3.y; a3.z += v3.z; a3.w += v3.w;
    }
    for (; i < e; i++) {
        int c = g_col[i];
        float4 v = *(const float4*)&in[(size_t)c * 128 + lane * 4];
        a0.x += v.x; a0.y += v.y; a0.z += v.z; a0.w += v.w;
    }
    float inv = g_invdeg[n];
    r.x = (a0.x + a1.x + a2.x + a3.x) * inv;
    r.y = (a0.y + a1.y + a2.y + a3.y) * inv;
    r.z = (a0.z + a1.z + a2.z + a3.z) * inv;
    r.w = (a0.w + a1.w + a2.w + a3.w) * inv;
}

__global__ void k_agg_flagged(const float* __restrict__ in, float* __restrict__ out) {
    int n = blockIdx.x * 8 + (threadIdx.x >> 5);
    if (n >= N_NODES) return;
    if (!g_flag[n]) return;
    int lane = threadIdx.x & 31;
    float4 r;
    agg_node(in, n, lane, r);
    *(float4*)&out[(size_t)n * 128 + lane * 4] = r;
}

__global__ void k_agg_target(const float* __restrict__ in, const int* __restrict__ tgt,
                             float* __restrict__ out) {
    int b = blockIdx.x * 8 + (threadIdx.x >> 5);
    if (b >= T_NODES) return;
    int lane = threadIdx.x & 31;
    int n = tgt[b];
    float4 r;
    agg_node(in, n, lane, r);
    *(float4*)&out[(size_t)b * 128 + lane * 4] = r;
}

// ---------------- predictor stage 1 (tf32 MMA) ----------------
#define FS_STR 140
#define WS_STR 264
__global__ void __launch_bounds__(256)
k_pred1(const float* __restrict__ m, const int* __restrict__ pair_s,
        const int* __restrict__ pair_t, const int* __restrict__ tgt,
        const float* __restrict__ mask, const float* __restrict__ Wp1) {
    int r0 = blockIdx.x * 64;
    int tid = threadIdx.x;
    int any = __syncthreads_or(tid < 64 && mask[r0 + tid] != 0.f);
    if (!any) return;  // pred2 zero-fills these rows

    __shared__ unsigned feats[64 * FS_STR];
    __shared__ unsigned ws[8 * WS_STR];

#pragma unroll
    for (int i = 0; i < 8; i++) {
        int idx = tid + i * 256;
        int r = idx >> 5, q = (idx & 31) << 2;
        int sN = pair_s[r0 + r];
        float4 v = *(const float4*)&m[(size_t)sN * 128 + q];
        uint4 u = make_uint4(f2tf(v.x), f2tf(v.y), f2tf(v.z), f2tf(v.w));
        *(uint4*)&feats[r * FS_STR + q] = u;
    }
    if (tid < 64) {
        int sN = pair_s[r0 + tid];
        int tN = tgt[pair_t[r0 + tid]];
        float4 ps = *(const float4*)&g_pe[sN * 4];
        float4 pt = *(const float4*)&g_pe[tN * 4];
        *(uint4*)&feats[tid * FS_STR + 128] =
            make_uint4(f2tf(ps.x), f2tf(ps.y), f2tf(ps.z), f2tf(ps.w));
        *(uint4*)&feats[tid * FS_STR + 132] =
            make_uint4(f2tf(pt.x), f2tf(pt.y), f2tf(pt.z), f2tf(pt.w));
    }

    int lane = tid & 31, wid = tid >> 5;
    int wm = wid & 1, wn = wid >> 1;
    int gid = lane >> 2, tig = lane & 3;

    float c[2][8][4];
#pragma unroll
    for (int mt = 0; mt < 2; mt++)
#pragma unroll
        for (int nt = 0; nt < 8; nt++)
#pragma unroll
            for (int q = 0; q < 4; q++) c[mt][nt][q] = 0.f;

    for (int ch = 0; ch < 17; ch++) {
        {
            int kk = tid >> 5, j = (tid & 31) << 3;
            const float* src = (ch < 16) ? &g_wf[(ch * 8 + kk) * 256 + j]
                                         : &Wp1[(192 + kk) * 256 + j];
            float4 v0 = *(const float4*)src;
            float4 v1 = *(const float4*)(src + 4);
            *(uint4*)&ws[kk * WS_STR + j] =
                make_uint4(f2tf(v0.x), f2tf(v0.y), f2tf(v0.z), f2tf(v0.w));
            *(uint4*)&ws[kk * WS_STR + j + 4] =
                make_uint4(f2tf(v1.x), f2tf(v1.y), f2tf(v1.z), f2tf(v1.w));
        }
        __syncthreads();
        int kb = ch * 8;
        unsigned a[2][4], b[8][2];
#pragma unroll
        for (int mt = 0; mt < 2; mt++) {
            int r = wm * 32 + mt * 16 + gid;
            a[mt][0] = feats[r * FS_STR + kb + tig];
            a[mt][1] = feats[(r + 8) * FS_STR + kb + tig];
            a[mt][2] = feats[r * FS_STR + kb + tig + 4];
            a[mt][3] = feats[(r + 8) * FS_STR + kb + tig + 4];
        }
#pragma unroll
        for (int nt = 0; nt < 8; nt++) {
            int bc = wn * 64 + nt * 8 + gid;
            b[nt][0] = ws[tig * WS_STR + bc];
            b[nt][1] = ws[(tig + 4) * WS_STR + bc];
        }
#pragma unroll
        for (int mt = 0; mt < 2; mt++)
#pragma unroll
            for (int nt = 0; nt < 8; nt++) mma8(c[mt][nt], a[mt], b[nt]);
        __syncthreads();
    }

#pragma unroll
    for (int mt = 0; mt < 2; mt++) {
        int r = r0 + wm * 32 + mt * 16 + gid;
#pragma unroll
        for (int nt = 0; nt < 8; nt++) {
            int col = wn * 64 + nt * 8 + 2 * tig;
            float2 zbv = *(const float2*)&g_zb[col];
            float2 v0 = make_float2(fmaxf(c[mt][nt][0] + zbv.x, 0.f),
                                    fmaxf(c[mt][nt][1] + zbv.y, 0.f));
            float2 v1 = make_float2(fmaxf(c[mt][nt][2] + zbv.x, 0.f),
                                    fmaxf(c[mt][nt][3] + zbv.y, 0.f));
            *(float2*)&g_hidden[(size_t)r * 256 + col] = v0;
            *(float2*)&g_hidden[(size_t)(r + 8) * 256 + col] = v1;
        }
    }
}

// ---------------- predictor stage 2 (tf32 MMA) ----------------
#define HS_STR 20
#define W2_STR 136
__global__ void __launch_bounds__(256)
k_pred2(const float* __restrict__ Wp2, const float* __restrict__ bp2,
        const float* __restrict__ mask, float* __restrict__ out) {
    int r0 = blockIdx.x * 64;
    int tid = threadIdx.x;
    __shared__ float ms[64];
    if (tid < 64) ms[tid] = mask[r0 + tid];
    int any = __syncthreads_or(tid < 64 && mask[r0 + tid] != 0.f);
    if (!any) {
        float4 zero = make_float4(0.f, 0.f, 0.f, 0.f);
#pragma unroll
        for (int i = 0; i < 8; i++) {
            int idx = tid + i * 256;
            *(float4*)&out[(size_t)r0 * 128 + idx * 4] = zero;
        }
        return;
    }

    __shared__ unsigned As[64 * HS_STR];
    __shared__ unsigned ws2[16 * W2_STR];

    int lane = tid & 31, wid = tid >> 5;
    int wm = wid & 1, wn = wid >> 1;
    int gid = lane >> 2, tig = lane & 3;

    float c[2][4][4];
#pragma unroll
    for (int mt = 0; mt < 2; mt++)
#pragma unroll
        for (int nt = 0; nt < 4; nt++)
#pragma unroll
            for (int q = 0; q < 4; q++) c[mt][nt][q] = 0.f;

    for (int ch = 0; ch < 16; ch++) {
        {
            int r = tid >> 2, kq = (tid & 3) << 2;
            float4 v = *(const float4*)&g_hidden[(size_t)(r0 + r) * 256 + ch * 16 + kq];
            *(uint4*)&As[r * HS_STR + kq] =
                make_uint4(f2tf(v.x), f2tf(v.y), f2tf(v.z), f2tf(v.w));
#pragma unroll
            for (int h = 0; h < 2; h++) {
                int kk = (tid >> 5) + h * 8;
                int j = (tid & 31) << 2;
                float4 w = *(const float4*)&Wp2[(size_t)(ch * 16 + kk) * 128 + j];
                *(uint4*)&ws2[kk * W2_STR + j] =
                    make_uint4(f2tf(w.x), f2tf(w.y), f2tf(w.z), f2tf(w.w));
            }
        }
        __syncthreads();
#pragma unroll
        for (int ks = 0; ks < 2; ks++) {
            int kb = ks * 8;
            unsigned a[2][4], b[4][2];
#pragma unroll
            for (int mt = 0; mt < 2; mt++) {
                int r = wm * 32 + mt * 16 + gid;
                a[mt][0] = As[r * HS_STR + kb + tig];
                a[mt][1] = As[(r + 8) * HS_STR + kb + tig];
                a[mt][2] = As[r * HS_STR + kb + tig + 4];
                a[mt][3] = As[(r + 8) * HS_STR + kb + tig + 4];
            }
#pragma unroll
            for (int nt = 0; nt < 4; nt++) {
                int bc = wn * 32 + nt * 8 + gid;
                b[nt][0] = ws2[(kb + tig) * W2_STR + bc];
                b[nt][1] = ws2[(kb + tig + 4) * W2_STR + bc];
            }
#pragma unroll
            for (int mt = 0; mt < 2; mt++)
#pragma unroll
                for (int nt = 0; nt < 4; nt++) mma8(c[mt][nt], a[mt], b[nt]);
        }
        __syncthreads();
    }

#pragma unroll
    for (int mt = 0; mt < 2; mt++) {
        int lr = wm * 32 + mt * 16 + gid;
        float m0v = ms[lr], m1v = ms[lr + 8];
#pragma unroll
        for (int nt = 0; nt < 4; nt++) {
            int col = wn * 32 + nt * 8 + 2 * tig;
            float2 bb = *(const float2*)&bp2[col];
            float2 v0 = make_float2((c[mt][nt][0] + bb.x) * m0v,
                                    (c[mt][nt][1] + bb.y) * m0v);
            float2 v1 = make_float2((c[mt][nt][2] + bb.x) * m1v,
                                    (c[mt][nt][3] + bb.y) * m1v);
            *(float2*)&out[(size_t)(r0 + lr) * 128 + col] = v0;
            *(float2*)&out[(size_t)(r0 + lr + 8) * 128 + col] = v1;
        }
    }
}

// ---------------- launch ----------------
extern "C" void kernel_launch(void* const* d_in, const int* in_sizes, int n_in,
                              void* d_out, int out_size) {
    const float* x            = (const float*)d_in[0];
    const float* masked_x     = (const float*)d_in[1];
    const float* pos_enc      = (const float*)d_in[2];
    const int*   edge_src     = (const int*)d_in[3];
    const int*   edge_dst     = (const int*)d_in[4];
    const int*   target_nodes = (const int*)d_in[5];
    const int*   pair_t       = (const int*)d_in[6];
    const int*   pair_s       = (const int*)d_in[7];
    const float* pair_mask    = (const float*)d_in[8];
    const float* W1t          = (const float*)d_in[9];
    const float* W2t          = (const float*)d_in[10];
    const float* W1c          = (const float*)d_in[11];
    const float* W2c          = (const float*)d_in[12];
    const float* Wpe          = (const float*)d_in[13];
    const float* z            = (const float*)d_in[14];
    const float* Wp1          = (const float*)d_in[15];
    const float* bp1          = (const float*)d_in[16];
    const float* Wp2          = (const float*)d_in[17];
    const float* bp2          = (const float*)d_in[18];
    float* out = (float*)d_out;

    float *buf1, *buf2, *buf3, *buf4, *tbuf;
    cudaGetSymbolAddress((void**)&buf1, g_buf1);
    cudaGetSymbolAddress((void**)&buf2, g_buf2);
    cudaGetSymbolAddress((void**)&buf3, g_buf3);
    cudaGetSymbolAddress((void**)&buf4, g_buf4);
    cudaGetSymbolAddress((void**)&tbuf, g_tbuf);

    cudaFuncSetAttribute(k_gemm_tf32, cudaFuncAttributeMaxDynamicSharedMemorySize,
                         GEMM_SMEM);

    const int TPB = 256;
    int gridN = (N_NODES + TPB - 1) / TPB;
    int gridE = (N_EDGES + TPB - 1) / TPB;
    int gridM = (N_NODES + 127) / 128;
    int gridA = (N_NODES + 7) / 8;

    // CSR build, big GEMM at launch slot 4 for the profiler window
    k_zero_cnt<<<gridN, TPB>>>();
    k_count<<<gridE, TPB>>>(edge_dst);
    k_scan<<<1, 1024>>>();
    k_gemm_tf32<<<gridM, 256, GEMM_SMEM>>>(x, W1t, buf1, N_NODES, 0);      // x @ W1t
    k_prep<<<gridN, TPB>>>();
    k_fill<<<gridE, TPB>>>(edge_src, edge_dst);
    k_flag<<<P_PAIRS / TPB, TPB>>>(pair_s, pair_mask);
    k_tflag<<<(T_NODES + TPB - 1) / TPB, TPB>>>(target_nodes);

    // tiny precomputes
    k_pe<<<gridN, TPB>>>(pos_enc, Wpe);
    k_zb<<<1, HP>>>(z, Wp1, bp1);
    k_wf<<<DIM, HP>>>(W2c, Wp1);

    // context first GEMM
    k_gemm_tf32<<<gridM, 256, GEMM_SMEM>>>(masked_x, W1c, buf2, N_NODES, 0);

    // fused first-layer aggregations: ht (tflag-restricted) + hc (full), both relu'd
    k_agg_dual<<<gridA, 256>>>(buf1, buf2, buf3, buf4);

    // target chain tail: agg at targets -> tiny GEMM straight into output embeddings
    k_agg_target<<<(T_NODES + 7) / 8, 256>>>(buf3, target_nodes, tbuf);
    k_gemm_tf32<<<T_NODES / 128, 256, GEMM_SMEM>>>(tbuf, W2t,
                                                   out + (size_t)P_PAIRS * DOUT,
                                                   T_NODES, 0);

    // context chain tail: flagged aggregation -> m
    k_agg_flagged<<<gridA, 256>>>(buf4, buf1);

    // predictor MLP (64-row tiles, mask-tile skipping)
    k_pred1<<<P_PAIRS / 64, 256>>>(buf1, pair_s, pair_t, target_nodes, pair_mask, Wp1);
    k_pred2<<<P_PAIRS / 64, 256>>>(Wp2, bp2, pair_mask, out);
}

// round 8
// speedup vs baseline: 1.3758x; 1.3758x over previous
#include <cuda_runtime.h>
#include <cstdint>

#define N_NODES 100000
#define N_EDGES 1600000
#define DIM     128
#define T_NODES 4096
#define P_PAIRS 131072
#define HP      256
#define DOUT    128
#define ZDIM    64

// ---------------- scratch (static device globals; no allocation) ----------------
__device__ int   g_cnt[N_NODES];
__device__ int   g_rowptr[N_NODES + 1];
__device__ int   g_cursor[N_NODES];
__device__ int   g_col[N_EDGES];
__device__ float g_invdeg[N_NODES];
__device__ unsigned char g_flag[N_NODES];
__device__ unsigned char g_tflag[N_NODES];
__device__ float g_pe[N_NODES * 4];
__device__ float g_zb[HP];
__device__ float g_wf[DIM * HP];                    // W2c @ Wp1[0:128]
__device__ float g_buf1[(size_t)N_NODES * DIM];
__device__ float g_buf2[(size_t)N_NODES * DIM];
__device__ float g_tbuf[(size_t)T_NODES * DIM];
__device__ float g_hidden[(size_t)P_PAIRS * HP];

// ---------------- tf32 helpers ----------------
__device__ __forceinline__ unsigned f2tf(float f) {
    unsigned u;
    asm("cvt.rna.tf32.f32 %0, %1;" : "=r"(u) : "f"(f));
    return u;
}
__device__ __forceinline__ void mma8(float* c, const unsigned* a, const unsigned* b) {
    asm volatile(
        "mma.sync.aligned.m16n8k8.row.col.f32.tf32.tf32.f32 "
        "{%0,%1,%2,%3},{%4,%5,%6,%7},{%8,%9},{%0,%1,%2,%3};"
        : "+f"(c[0]), "+f"(c[1]), "+f"(c[2]), "+f"(c[3])
        : "r"(a[0]), "r"(a[1]), "r"(a[2]), "r"(a[3]), "r"(b[0]), "r"(b[1]));
}

// ---------------- CSR build ----------------
__global__ void k_zero_cnt() {
    int i = blockIdx.x * blockDim.x + threadIdx.x;
    if (i < N_NODES) { g_cnt[i] = 0; g_flag[i] = 0; g_tflag[i] = 0; }
}

__global__ void k_count(const int* __restrict__ dst) {
    int e = blockIdx.x * blockDim.x + threadIdx.x;
    if (e < N_EDGES) atomicAdd(&g_cnt[dst[e]], 1);
}

__global__ void k_scan() {
    __shared__ int sums[1024];
    const int CH = (N_NODES + 1024) / 1024;
    int t = threadIdx.x;
    int base = t * CH;
    int s = 0;
    for (int i = 0; i < CH; i++) {
        int idx = base + i;
        if (idx < N_NODES) s += g_cnt[idx];
    }
    sums[t] = s;
    __syncthreads();
    for (int off = 1; off < 1024; off <<= 1) {
        int v = (t >= off) ? sums[t - off] : 0;
        __syncthreads();
        sums[t] += v;
        __syncthreads();
    }
    int run = sums[t] - s;
    for (int i = 0; i < CH; i++) {
        int idx = base + i;
        if (idx <= N_NODES) g_rowptr[idx] = run;
        if (idx < N_NODES) run += g_cnt[idx];
    }
}

__global__ void k_prep() {
    int i = blockIdx.x * blockDim.x + threadIdx.x;
    if (i < N_NODES) {
        g_cursor[i] = g_rowptr[i];
        int c = g_cnt[i];
        g_invdeg[i] = 1.0f / (float)(c > 0 ? c : 1);
    }
}

__global__ void k_fill(const int* __restrict__ src, const int* __restrict__ dst) {
    int e = blockIdx.x * blockDim.x + threadIdx.x;
    if (e < N_EDGES) {
        int pos = atomicAdd(&g_cursor[dst[e]], 1);
        g_col[pos] = src[e];
    }
}

__global__ void k_flag(const int* __restrict__ pair_s, const float* __restrict__ mask) {
    int i = blockIdx.x * blockDim.x + threadIdx.x;
    if (i < P_PAIRS && mask[i] != 0.f) g_flag[pair_s[i]] = 1;
}

// mark in-neighbors of target nodes (rows of h_t actually consumed by agg_target)
__global__ void k_tflag(const int* __restrict__ tgt) {
    int b = blockIdx.x * blockDim.x + threadIdx.x;
    if (b >= T_NODES) return;
    int n = tgt[b];
    int e = g_rowptr[n + 1];
    for (int i = g_rowptr[n]; i < e; i++) g_tflag[g_col[i]] = 1;
}

// ---------------- tiny precomputes ----------------
__global__ void k_pe(const float* __restrict__ pos_enc, const float* __restrict__ Wpe) {
    int n = blockIdx.x * blockDim.x + threadIdx.x;
    if (n >= N_NODES) return;
    float4 p = *(const float4*)&pos_enc[n * 4];
#pragma unroll
    for (int i = 0; i < 4; i++) {
        g_pe[n * 4 + i] = p.x * Wpe[i * 4 + 0] + p.y * Wpe[i * 4 + 1] +
                          p.z * Wpe[i * 4 + 2] + p.w * Wpe[i * 4 + 3];
    }
}

__global__ void k_zb(const float* __restrict__ z, const float* __restrict__ Wp1,
                     const float* __restrict__ bp1) {
    int j = threadIdx.x;
    float acc = bp1[j];
    for (int i = 0; i < ZDIM; i++) acc = fmaf(z[i], Wp1[(128 + i) * HP + j], acc);
    g_zb[j] = acc;
}

__global__ void k_wf(const float* __restrict__ W2c, const float* __restrict__ Wp1) {
    int i = blockIdx.x;
    int j = threadIdx.x;
    float acc = 0.f;
    for (int d = 0; d < DIM; d++) acc = fmaf(W2c[i * DIM + d], Wp1[d * HP + j], acc);
    g_wf[i * HP + j] = acc;
}

// ---------------- tf32 GEMM (R4-proven): C[M,128] = (relu?)(A[M,128] @ B[128,128]) --
// 128x128 block, 256 threads (8 warps as 4x2), warp tile 32x64, mma m16n8k8.
#define AS_STR 36
#define BS_STR 136
__global__ void __launch_bounds__(256)
k_gemm_tf32(const float* __restrict__ A, const float* __restrict__ B,
            float* __restrict__ C, int M, int relu) {
    __shared__ unsigned As[128 * AS_STR];
    __shared__ unsigned Bs[32 * BS_STR];
    int m0 = blockIdx.x * 128;
    int tid = threadIdx.x;
    int lane = tid & 31, wid = tid >> 5;
    int wm = wid & 3, wn = wid >> 2;      // rows wm*32, cols wn*64
    int gid = lane >> 2, tig = lane & 3;

    float c[2][8][4];
#pragma unroll
    for (int mt = 0; mt < 2; mt++)
#pragma unroll
        for (int nt = 0; nt < 8; nt++)
#pragma unroll
            for (int q = 0; q < 4; q++) c[mt][nt][q] = 0.f;

    int ar = tid >> 1, acb = (tid & 1) * 16;   // A stage: 128 rows x 32 k
    int br = tid >> 3, bcb = (tid & 7) * 16;   // B stage: 32 k x 128 cols

    for (int kc = 0; kc < 128; kc += 32) {
        {
            int grow = m0 + ar;
#pragma unroll
            for (int q = 0; q < 4; q++) {
                float4 v = (grow < M)
                    ? *(const float4*)&A[(size_t)grow * 128 + kc + acb + q * 4]
                    : make_float4(0.f, 0.f, 0.f, 0.f);
                uint4 u = make_uint4(f2tf(v.x), f2tf(v.y), f2tf(v.z), f2tf(v.w));
                *(uint4*)&As[ar * AS_STR + acb + q * 4] = u;
            }
#pragma unroll
            for (int q = 0; q < 4; q++) {
                float4 v = *(const float4*)&B[(size_t)(kc + br) * 128 + bcb + q * 4];
                uint4 u = make_uint4(f2tf(v.x), f2tf(v.y), f2tf(v.z), f2tf(v.w));
                *(uint4*)&Bs[br * BS_STR + bcb + q * 4] = u;
            }
        }
        __syncthreads();
#pragma unroll
        for (int ks = 0; ks < 4; ks++) {
            int kb = ks * 8;
            unsigned a[2][4], b[8][2];
#pragma unroll
            for (int mt = 0; mt < 2; mt++) {
                int r = wm * 32 + mt * 16 + gid;
                a[mt][0] = As[r * AS_STR + kb + tig];
                a[mt][1] = As[(r + 8) * AS_STR + kb + tig];
                a[mt][2] = As[r * AS_STR + kb + tig + 4];
                a[mt][3] = As[(r + 8) * AS_STR + kb + tig + 4];
            }
#pragma unroll
            for (int nt = 0; nt < 8; nt++) {
                int bc = wn * 64 + nt * 8 + gid;
                b[nt][0] = Bs[(kb + tig) * BS_STR + bc];
                b[nt][1] = Bs[(kb + tig + 4) * BS_STR + bc];
            }
#pragma unroll
            for (int mt = 0; mt < 2; mt++)
#pragma unroll
                for (int nt = 0; nt < 8; nt++) mma8(c[mt][nt], a[mt], b[nt]);
        }
        __syncthreads();
    }

#pragma unroll
    for (int mt = 0; mt < 2; mt++) {
        int r = m0 + wm * 32 + mt * 16 + gid;
#pragma unroll
        for (int nt = 0; nt < 8; nt++) {
            int col = wn * 64 + nt * 8 + 2 * tig;
            float2 v0 = make_float2(c[mt][nt][0], c[mt][nt][1]);
            float2 v1 = make_float2(c[mt][nt][2], c[mt][nt][3]);
            if (relu) {
                v0.x = fmaxf(v0.x, 0.f); v0.y = fmaxf(v0.y, 0.f);
                v1.x = fmaxf(v1.x, 0.f); v1.y = fmaxf(v1.y, 0.f);
            }
            if (r < M)     *(float2*)&C[(size_t)r * 128 + col] = v0;
            if (r + 8 < M) *(float2*)&C[(size_t)(r + 8) * 128 + col] = v1;
        }
    }
}

// ---------------- CSR gather-aggregation: warp per node, float4 lanes ----------------
__device__ __forceinline__ void agg_node(const float* __restrict__ in, int n, int lane,
                                         float4& r) {
    int s = g_rowptr[n], e = g_rowptr[n + 1];
    float4 a0 = make_float4(0.f, 0.f, 0.f, 0.f), a1 = a0, a2 = a0, a3 = a0;
    int i = s;
    for (; i + 4 <= e; i += 4) {
        int c0 = g_col[i], c1 = g_col[i + 1], c2 = g_col[i + 2], c3 = g_col[i + 3];
        float4 v0 = *(const float4*)&in[(size_t)c0 * 128 + lane * 4];
        float4 v1 = *(const float4*)&in[(size_t)c1 * 128 + lane * 4];
        float4 v2 = *(const float4*)&in[(size_t)c2 * 128 + lane * 4];
        float4 v3 = *(const float4*)&in[(size_t)c3 * 128 + lane * 4];
        a0.x += v0.x; a0.y += v0.y; a0.z += v0.z; a0.w += v0.w;
        a1.x += v1.x; a1.y += v1.y; a1.z += v1.z; a1.w += v1.w;
        a2.x += v2.x; a2.y += v2.y; a2.z += v2.z; a2.w += v2.w;
        a3.x += v3.x; a3.y += v3.y; a3.z += v3.z; a3.w += v3.w;
    }
    for (; i < e; i++) {
        int c = g_col[i];
        float4 v = *(const float4*)&in[(size_t)c * 128 + lane * 4];
        a0.x += v.x; a0.y += v.y; a0.z += v.z; a0.w += v.w;
    }
    float inv = g_invdeg[n];
    r.x = (a0.x + a1.x + a2.x + a3.x) * inv;
    r.y = (a0.y + a1.y + a2.y + a3.y) * inv;
    r.z = (a0.z + a1.z + a2.z + a3.z) * inv;
    r.w = (a0.w + a1.w + a2.w + a3.w) * inv;
}

__global__ void k_agg(const float* __restrict__ in, float* __restrict__ out, int relu) {
    int n = blockIdx.x * 8 + (threadIdx.x >> 5);
    if (n >= N_NODES) return;
    int lane = threadIdx.x & 31;
    float4 r;
    agg_node(in, n, lane, r);
    if (relu) {
        r.x = fmaxf(r.x, 0.f); r.y = fmaxf(r.y, 0.f);
        r.z = fmaxf(r.z, 0.f); r.w = fmaxf(r.w, 0.f);
    }
    *(float4*)&out[(size_t)n * 128 + lane * 4] = r;
}

// target-chain first agg, restricted to in-neighbors of target nodes
__global__ void k_agg_tflagged(const float* __restrict__ in, float* __restrict__ out) {
    int n = blockIdx.x * 8 + (threadIdx.x >> 5);
    if (n >= N_NODES) return;
    if (!g_tflag[n]) return;
    int lane = threadIdx.x & 31;
    float4 r;
    agg_node(in, n, lane, r);
    r.x = fmaxf(r.x, 0.f); r.y = fmaxf(r.y, 0.f);
    r.z = fmaxf(r.z, 0.f); r.w = fmaxf(r.w, 0.f);
    *(float4*)&out[(size_t)n * 128 + lane * 4] = r;
}

__global__ void k_agg_flagged(const float* __restrict__ in, float* __restrict__ out) {
    int n = blockIdx.x * 8 + (threadIdx.x >> 5);
    if (n >= N_NODES) return;
    if (!g_flag[n]) return;
    int lane = threadIdx.x & 31;
    float4 r;
    agg_node(in, n, lane, r);
    *(float4*)&out[(size_t)n * 128 + lane * 4] = r;
}

__global__ void k_agg_target(const float* __restrict__ in, const int* __restrict__ tgt,
                             float* __restrict__ out) {
    int b = blockIdx.x * 8 + (threadIdx.x >> 5);
    if (b >= T_NODES) return;
    int lane = threadIdx.x & 31;
    int n = tgt[b];
    float4 r;
    agg_node(in, n, lane, r);
    *(float4*)&out[(size_t)b * 128 + lane * 4] = r;
}

// ---------------- predictor stage 1 (tf32 MMA) ----------------
#define FS_STR 140
#define WS_STR 264
__global__ void __launch_bounds__(256)
k_pred1(const float* __restrict__ m, const int* __restrict__ pair_s,
        const int* __restrict__ pair_t, const int* __restrict__ tgt,
        const float* __restrict__ mask, const float* __restrict__ Wp1) {
    int r0 = blockIdx.x * 64;
    int tid = threadIdx.x;
    int any = __syncthreads_or(tid < 64 && mask[r0 + tid] != 0.f);
    if (!any) return;  // pred2 zero-fills these rows

    __shared__ unsigned feats[64 * FS_STR];
    __shared__ unsigned ws[8 * WS_STR];

#pragma unroll
    for (int i = 0; i < 8; i++) {
        int idx = tid + i * 256;
        int r = idx >> 5, q = (idx & 31) << 2;
        int sN = pair_s[r0 + r];
        float4 v = *(const float4*)&m[(size_t)sN * 128 + q];
        uint4 u = make_uint4(f2tf(v.x), f2tf(v.y), f2tf(v.z), f2tf(v.w));
        *(uint4*)&feats[r * FS_STR + q] = u;
    }
    if (tid < 64) {
        int sN = pair_s[r0 + tid];
        int tN = tgt[pair_t[r0 + tid]];
        float4 ps = *(const float4*)&g_pe[sN * 4];
        float4 pt = *(const float4*)&g_pe[tN * 4];
        *(uint4*)&feats[tid * FS_STR + 128] =
            make_uint4(f2tf(ps.x), f2tf(ps.y), f2tf(ps.z), f2tf(ps.w));
        *(uint4*)&feats[tid * FS_STR + 132] =
            make_uint4(f2tf(pt.x), f2tf(pt.y), f2tf(pt.z), f2tf(pt.w));
    }

    int lane = tid & 31, wid = tid >> 5;
    int wm = wid & 1, wn = wid >> 1;
    int gid = lane >> 2, tig = lane & 3;

    float c[2][8][4];
#pragma unroll
    for (int mt = 0; mt < 2; mt++)
#pragma unroll
        for (int nt = 0; nt < 8; nt++)
#pragma unroll
            for (int q = 0; q < 4; q++) c[mt][nt][q] = 0.f;

    for (int ch = 0; ch < 17; ch++) {
        {
            int kk = tid >> 5, j = (tid & 31) << 3;
            const float* src = (ch < 16) ? &g_wf[(ch * 8 + kk) * 256 + j]
                                         : &Wp1[(192 + kk) * 256 + j];
            float4 v0 = *(const float4*)src;
            float4 v1 = *(const float4*)(src + 4);
            *(uint4*)&ws[kk * WS_STR + j] =
                make_uint4(f2tf(v0.x), f2tf(v0.y), f2tf(v0.z), f2tf(v0.w));
            *(uint4*)&ws[kk * WS_STR + j + 4] =
                make_uint4(f2tf(v1.x), f2tf(v1.y), f2tf(v1.z), f2tf(v1.w));
        }
        __syncthreads();
        int kb = ch * 8;
        unsigned a[2][4], b[8][2];
#pragma unroll
        for (int mt = 0; mt < 2; mt++) {
            int r = wm * 32 + mt * 16 + gid;
            a[mt][0] = feats[r * FS_STR + kb + tig];
            a[mt][1] = feats[(r + 8) * FS_STR + kb + tig];
            a[mt][2] = feats[r * FS_STR + kb + tig + 4];
            a[mt][3] = feats[(r + 8) * FS_STR + kb + tig + 4];
        }
#pragma unroll
        for (int nt = 0; nt < 8; nt++) {
            int bc = wn * 64 + nt * 8 + gid;
            b[nt][0] = ws[tig * WS_STR + bc];
            b[nt][1] = ws[(tig + 4) * WS_STR + bc];
        }
#pragma unroll
        for (int mt = 0; mt < 2; mt++)
#pragma unroll
            for (int nt = 0; nt < 8; nt++) mma8(c[mt][nt], a[mt], b[nt]);
        __syncthreads();
    }

#pragma unroll
    for (int mt = 0; mt < 2; mt++) {
        int r = r0 + wm * 32 + mt * 16 + gid;
#pragma unroll
        for (int nt = 0; nt < 8; nt++) {
            int col = wn * 64 + nt * 8 + 2 * tig;
            float2 zbv = *(const float2*)&g_zb[col];
            float2 v0 = make_float2(fmaxf(c[mt][nt][0] + zbv.x, 0.f),
                                    fmaxf(c[mt][nt][1] + zbv.y, 0.f));
            float2 v1 = make_float2(fmaxf(c[mt][nt][2] + zbv.x, 0.f),
                                    fmaxf(c[mt][nt][3] + zbv.y, 0.f));
            *(float2*)&g_hidden[(size_t)r * 256 + col] = v0;
            *(float2*)&g_hidden[(size_t)(r + 8) * 256 + col] = v1;
        }
    }
}

// ---------------- predictor stage 2 (tf32 MMA) ----------------
#define HS_STR 20
#define W2_STR 136
__global__ void __launch_bounds__(256)
k_pred2(const float* __restrict__ Wp2, const float* __restrict__ bp2,
        const float* __restrict__ mask, float* __restrict__ out) {
    int r0 = blockIdx.x * 64;
    int tid = threadIdx.x;
    __shared__ float ms[64];
    if (tid < 64) ms[tid] = mask[r0 + tid];
    int any = __syncthreads_or(tid < 64 && mask[r0 + tid] != 0.f);
    if (!any) {
        float4 zero = make_float4(0.f, 0.f, 0.f, 0.f);
#pragma unroll
        for (int i = 0; i < 8; i++) {
            int idx = tid + i * 256;
            *(float4*)&out[(size_t)r0 * 128 + idx * 4] = zero;
        }
        return;
    }

    __shared__ unsigned As[64 * HS_STR];
    __shared__ unsigned ws2[16 * W2_STR];

    int lane = tid & 31, wid = tid >> 5;
    int wm = wid & 1, wn = wid >> 1;
    int gid = lane >> 2, tig = lane & 3;

    float c[2][4][4];
#pragma unroll
    for (int mt = 0; mt < 2; mt++)
#pragma unroll
        for (int nt = 0; nt < 4; nt++)
#pragma unroll
            for (int q = 0; q < 4; q++) c[mt][nt][q] = 0.f;

    for (int ch = 0; ch < 16; ch++) {
        {
            int r = tid >> 2, kq = (tid & 3) << 2;
            float4 v = *(const float4*)&g_hidden[(size_t)(r0 + r) * 256 + ch * 16 + kq];
            *(uint4*)&As[r * HS_STR + kq] =
                make_uint4(f2tf(v.x), f2tf(v.y), f2tf(v.z), f2tf(v.w));
#pragma unroll
            for (int h = 0; h < 2; h++) {
                int kk = (tid >> 5) + h * 8;
                int j = (tid & 31) << 2;
                float4 w = *(const float4*)&Wp2[(size_t)(ch * 16 + kk) * 128 + j];
                *(uint4*)&ws2[kk * W2_STR + j] =
                    make_uint4(f2tf(w.x), f2tf(w.y), f2tf(w.z), f2tf(w.w));
            }
        }
        __syncthreads();
#pragma unroll
        for (int ks = 0; ks < 2; ks++) {
            int kb = ks * 8;
            unsigned a[2][4], b[4][2];
#pragma unroll
            for (int mt = 0; mt < 2; mt++) {
                int r = wm * 32 + mt * 16 + gid;
                a[mt][0] = As[r * HS_STR + kb + tig];
                a[mt][1] = As[(r + 8) * HS_STR + kb + tig];
                a[mt][2] = As[r * HS_STR + kb + tig + 4];
                a[mt][3] = As[(r + 8) * HS_STR + kb + tig + 4];
            }
#pragma unroll
            for (int nt = 0; nt < 4; nt++) {
                int bc = wn * 32 + nt * 8 + gid;
                b[nt][0] = ws2[(kb + tig) * W2_STR + bc];
                b[nt][1] = ws2[(kb + tig + 4) * W2_STR + bc];
            }
#pragma unroll
            for (int mt = 0; mt < 2; mt++)
#pragma unroll
                for (int nt = 0; nt < 4; nt++) mma8(c[mt][nt], a[mt], b[nt]);
        }
        __syncthreads();
    }

#pragma unroll
    for (int mt = 0; mt < 2; mt++) {
        int lr = wm * 32 + mt * 16 + gid;
        float m0v = ms[lr], m1v = ms[lr + 8];
#pragma unroll
        for (int nt = 0; nt < 4; nt++) {
            int col = wn * 32 + nt * 8 + 2 * tig;
            float2 bb = *(const float2*)&bp2[col];
            float2 v0 = make_float2((c[mt][nt][0] + bb.x) * m0v,
                                    (c[mt][nt][1] + bb.y) * m0v);
            float2 v1 = make_float2((c[mt][nt][2] + bb.x) * m1v,
                                    (c[mt][nt][3] + bb.y) * m1v);
            *(float2*)&out[(size_t)(r0 + lr) * 128 + col] = v0;
            *(float2*)&out[(size_t)(r0 + lr + 8) * 128 + col] = v1;
        }
    }
}

// ---------------- launch ----------------
extern "C" void kernel_launch(void* const* d_in, const int* in_sizes, int n_in,
                              void* d_out, int out_size) {
    const float* x            = (const float*)d_in[0];
    const float* masked_x     = (const float*)d_in[1];
    const float* pos_enc      = (const float*)d_in[2];
    const int*   edge_src     = (const int*)d_in[3];
    const int*   edge_dst     = (const int*)d_in[4];
    const int*   target_nodes = (const int*)d_in[5];
    const int*   pair_t       = (const int*)d_in[6];
    const int*   pair_s       = (const int*)d_in[7];
    const float* pair_mask    = (const float*)d_in[8];
    const float* W1t          = (const float*)d_in[9];
    const float* W2t          = (const float*)d_in[10];
    const float* W1c          = (const float*)d_in[11];
    const float* W2c          = (const float*)d_in[12];
    const float* Wpe          = (const float*)d_in[13];
    const float* z            = (const float*)d_in[14];
    const float* Wp1          = (const float*)d_in[15];
    const float* bp1          = (const float*)d_in[16];
    const float* Wp2          = (const float*)d_in[17];
    const float* bp2          = (const float*)d_in[18];
    float* out = (float*)d_out;

    float *buf1, *buf2, *tbuf;
    cudaGetSymbolAddress((void**)&buf1, g_buf1);
    cudaGetSymbolAddress((void**)&buf2, g_buf2);
    cudaGetSymbolAddress((void**)&tbuf, g_tbuf);

    const int TPB = 256;
    int gridN = (N_NODES + TPB - 1) / TPB;
    int gridE = (N_EDGES + TPB - 1) / TPB;
    int gridM = (N_NODES + 127) / 128;
    int gridA = (N_NODES + 7) / 8;

    // CSR build, big GEMM at launch slot 4 for the profiler window
    k_zero_cnt<<<gridN, TPB>>>();
    k_count<<<gridE, TPB>>>(edge_dst);
    k_scan<<<1, 1024>>>();
    k_gemm_tf32<<<gridM, 256>>>(x, W1t, buf2, N_NODES, 0);     // x @ W1t
    k_prep<<<gridN, TPB>>>();
    k_fill<<<gridE, TPB>>>(edge_src, edge_dst);
    k_flag<<<P_PAIRS / TPB, TPB>>>(pair_s, pair_mask);
    k_tflag<<<(T_NODES + TPB - 1) / TPB, TPB>>>(target_nodes);

    // tiny precomputes
    k_pe<<<gridN, TPB>>>(pos_enc, Wpe);
    k_zb<<<1, HP>>>(z, Wp1, bp1);
    k_wf<<<DIM, HP>>>(W2c, Wp1);

    // target GCN: h = relu(agg(xW1)) at tflag nodes only ; out_emb = agg(h)[targets] @ W2t
    k_agg_tflagged<<<gridA, 256>>>(buf2, buf1);
    k_agg_target<<<(T_NODES + 7) / 8, 256>>>(buf1, target_nodes, tbuf);
    k_gemm_tf32<<<T_NODES / 128, 256>>>(tbuf, W2t, out + (size_t)P_PAIRS * DOUT,
                                        T_NODES, 0);

    // context GCN: h_c = relu(agg(mxW1c)) ; m = agg(h_c) restricted to flagged nodes
    k_gemm_tf32<<<gridM, 256>>>(masked_x, W1c, buf2, N_NODES, 0);
    k_agg<<<gridA, 256>>>(buf2, buf1, 1);
    k_agg_flagged<<<gridA, 256>>>(buf1, buf2);   // m -> buf2

    // predictor MLP (64-row tiles, mask-tile skipping)
    k_pred1<<<P_PAIRS / 64, 256>>>(buf2, pair_s, pair_t, target_nodes, pair_mask, Wp1);
    k_pred2<<<P_PAIRS / 64, 256>>>(Wp2, bp2, pair_mask, out);
}

// round 9
// speedup vs baseline: 1.4150x; 1.0285x over previous
#include <cuda_runtime.h>
#include <cstdint>

#define N_NODES 100000
#define N_EDGES 1600000
#define DIM     128
#define T_NODES 4096
#define P_PAIRS 131072
#define HP      256
#define DOUT    128
#define ZDIM    64

// ---------------- scratch (static device globals; no allocation) ----------------
__device__ int   g_cnt[N_NODES];
__device__ int   g_rowptr[N_NODES + 1];
__device__ int   g_cursor[N_NODES];
__device__ int   g_col[N_EDGES];
__device__ float g_invdeg[N_NODES];
__device__ unsigned char g_flag[N_NODES];
__device__ unsigned char g_tflag[N_NODES];
__device__ float g_pe[N_NODES * 4];
__device__ float g_zb[HP];
__device__ float g_wf[DIM * HP];                    // W2c @ Wp1[0:128]
__device__ float g_buf1[(size_t)N_NODES * DIM];
__device__ float g_buf2[(size_t)N_NODES * DIM];
__device__ float g_tbuf[(size_t)T_NODES * DIM];

// ---------------- tf32 helpers ----------------
__device__ __forceinline__ unsigned f2tf(float f) {
    unsigned u;
    asm("cvt.rna.tf32.f32 %0, %1;" : "=r"(u) : "f"(f));
    return u;
}
__device__ __forceinline__ void mma8(float* c, const unsigned* a, const unsigned* b) {
    asm volatile(
        "mma.sync.aligned.m16n8k8.row.col.f32.tf32.tf32.f32 "
        "{%0,%1,%2,%3},{%4,%5,%6,%7},{%8,%9},{%0,%1,%2,%3};"
        : "+f"(c[0]), "+f"(c[1]), "+f"(c[2]), "+f"(c[3])
        : "r"(a[0]), "r"(a[1]), "r"(a[2]), "r"(a[3]), "r"(b[0]), "r"(b[1]));
}

// ---------------- CSR build ----------------
__global__ void k_zero_cnt() {
    int i = blockIdx.x * blockDim.x + threadIdx.x;
    if (i < N_NODES) { g_cnt[i] = 0; g_flag[i] = 0; g_tflag[i] = 0; }
}

__global__ void k_count(const int* __restrict__ dst) {
    int e = blockIdx.x * blockDim.x + threadIdx.x;
    if (e < N_EDGES) atomicAdd(&g_cnt[dst[e]], 1);
}

__global__ void k_scan() {
    __shared__ int sums[1024];
    const int CH = (N_NODES + 1024) / 1024;
    int t = threadIdx.x;
    int base = t * CH;
    int s = 0;
    for (int i = 0; i < CH; i++) {
        int idx = base + i;
        if (idx < N_NODES) s += g_cnt[idx];
    }
    sums[t] = s;
    __syncthreads();
    for (int off = 1; off < 1024; off <<= 1) {
        int v = (t >= off) ? sums[t - off] : 0;
        __syncthreads();
        sums[t] += v;
        __syncthreads();
    }
    int run = sums[t] - s;
    for (int i = 0; i < CH; i++) {
        int idx = base + i;
        if (idx <= N_NODES) g_rowptr[idx] = run;
        if (idx < N_NODES) run += g_cnt[idx];
    }
}

__global__ void k_prep() {
    int i = blockIdx.x * blockDim.x + threadIdx.x;
    if (i < N_NODES) {
        g_cursor[i] = g_rowptr[i];
        int c = g_cnt[i];
        g_invdeg[i] = 1.0f / (float)(c > 0 ? c : 1);
    }
}

__global__ void k_fill(const int* __restrict__ src, const int* __restrict__ dst) {
    int e = blockIdx.x * blockDim.x + threadIdx.x;
    if (e < N_EDGES) {
        int pos = atomicAdd(&g_cursor[dst[e]], 1);
        g_col[pos] = src[e];
    }
}

__global__ void k_flag(const int* __restrict__ pair_s, const float* __restrict__ mask) {
    int i = blockIdx.x * blockDim.x + threadIdx.x;
    if (i < P_PAIRS && mask[i] != 0.f) g_flag[pair_s[i]] = 1;
}

// mark in-neighbors of target nodes (rows of h_t actually consumed by agg_target)
__global__ void k_tflag(const int* __restrict__ tgt) {
    int b = blockIdx.x * blockDim.x + threadIdx.x;
    if (b >= T_NODES) return;
    int n = tgt[b];
    int e = g_rowptr[n + 1];
    for (int i = g_rowptr[n]; i < e; i++) g_tflag[g_col[i]] = 1;
}

// ---------------- tiny precomputes ----------------
__global__ void k_pe(const float* __restrict__ pos_enc, const float* __restrict__ Wpe) {
    int n = blockIdx.x * blockDim.x + threadIdx.x;
    if (n >= N_NODES) return;
    float4 p = *(const float4*)&pos_enc[n * 4];
#pragma unroll
    for (int i = 0; i < 4; i++) {
        g_pe[n * 4 + i] = p.x * Wpe[i * 4 + 0] + p.y * Wpe[i * 4 + 1] +
                          p.z * Wpe[i * 4 + 2] + p.w * Wpe[i * 4 + 3];
    }
}

__global__ void k_zb(const float* __restrict__ z, const float* __restrict__ Wp1,
                     const float* __restrict__ bp1) {
    int j = threadIdx.x;
    float acc = bp1[j];
    for (int i = 0; i < ZDIM; i++) acc = fmaf(z[i], Wp1[(128 + i) * HP + j], acc);
    g_zb[j] = acc;
}

__global__ void k_wf(const float* __restrict__ W2c, const float* __restrict__ Wp1) {
    int i = blockIdx.x;
    int j = threadIdx.x;
    float acc = 0.f;
    for (int d = 0; d < DIM; d++) acc = fmaf(W2c[i * DIM + d], Wp1[d * HP + j], acc);
    g_wf[i * HP + j] = acc;
}

// ---------------- tf32 GEMM (R4-proven): C[M,128] = (relu?)(A[M,128] @ B[128,128]) --
#define AS_STR 36
#define BS_STR 136
__global__ void __launch_bounds__(256)
k_gemm_tf32(const float* __restrict__ A, const float* __restrict__ B,
            float* __restrict__ C, int M, int relu) {
    __shared__ unsigned As[128 * AS_STR];
    __shared__ unsigned Bs[32 * BS_STR];
    int m0 = blockIdx.x * 128;
    int tid = threadIdx.x;
    int lane = tid & 31, wid = tid >> 5;
    int wm = wid & 3, wn = wid >> 2;      // rows wm*32, cols wn*64
    int gid = lane >> 2, tig = lane & 3;

    float c[2][8][4];
#pragma unroll
    for (int mt = 0; mt < 2; mt++)
#pragma unroll
        for (int nt = 0; nt < 8; nt++)
#pragma unroll
            for (int q = 0; q < 4; q++) c[mt][nt][q] = 0.f;

    int ar = tid >> 1, acb = (tid & 1) * 16;   // A stage: 128 rows x 32 k
    int br = tid >> 3, bcb = (tid & 7) * 16;   // B stage: 32 k x 128 cols

    for (int kc = 0; kc < 128; kc += 32) {
        {
            int grow = m0 + ar;
#pragma unroll
            for (int q = 0; q < 4; q++) {
                float4 v = (grow < M)
                    ? *(const float4*)&A[(size_t)grow * 128 + kc + acb + q * 4]
                    : make_float4(0.f, 0.f, 0.f, 0.f);
                uint4 u = make_uint4(f2tf(v.x), f2tf(v.y), f2tf(v.z), f2tf(v.w));
                *(uint4*)&As[ar * AS_STR + acb + q * 4] = u;
            }
#pragma unroll
            for (int q = 0; q < 4; q++) {
                float4 v = *(const float4*)&B[(size_t)(kc + br) * 128 + bcb + q * 4];
                uint4 u = make_uint4(f2tf(v.x), f2tf(v.y), f2tf(v.z), f2tf(v.w));
                *(uint4*)&Bs[br * BS_STR + bcb + q * 4] = u;
            }
        }
        __syncthreads();
#pragma unroll
        for (int ks = 0; ks < 4; ks++) {
            int kb = ks * 8;
            unsigned a[2][4], b[8][2];
#pragma unroll
            for (int mt = 0; mt < 2; mt++) {
                int r = wm * 32 + mt * 16 + gid;
                a[mt][0] = As[r * AS_STR + kb + tig];
                a[mt][1] = As[(r + 8) * AS_STR + kb + tig];
                a[mt][2] = As[r * AS_STR + kb + tig + 4];
                a[mt][3] = As[(r + 8) * AS_STR + kb + tig + 4];
            }
#pragma unroll
            for (int nt = 0; nt < 8; nt++) {
                int bc = wn * 64 + nt * 8 + gid;
                b[nt][0] = Bs[(kb + tig) * BS_STR + bc];
                b[nt][1] = Bs[(kb + tig + 4) * BS_STR + bc];
            }
#pragma unroll
            for (int mt = 0; mt < 2; mt++)
#pragma unroll
                for (int nt = 0; nt < 8; nt++) mma8(c[mt][nt], a[mt], b[nt]);
        }
        __syncthreads();
    }

#pragma unroll
    for (int mt = 0; mt < 2; mt++) {
        int r = m0 + wm * 32 + mt * 16 + gid;
#pragma unroll
        for (int nt = 0; nt < 8; nt++) {
            int col = wn * 64 + nt * 8 + 2 * tig;
            float2 v0 = make_float2(c[mt][nt][0], c[mt][nt][1]);
            float2 v1 = make_float2(c[mt][nt][2], c[mt][nt][3]);
            if (relu) {
                v0.x = fmaxf(v0.x, 0.f); v0.y = fmaxf(v0.y, 0.f);
                v1.x = fmaxf(v1.x, 0.f); v1.y = fmaxf(v1.y, 0.f);
            }
            if (r < M)     *(float2*)&C[(size_t)r * 128 + col] = v0;
            if (r + 8 < M) *(float2*)&C[(size_t)(r + 8) * 128 + col] = v1;
        }
    }
}

// ---------------- CSR gather-aggregation: warp per node, float4 lanes ----------------
__device__ __forceinline__ void agg_node(const float* __restrict__ in, int n, int lane,
                                         float4& r) {
    int s = g_rowptr[n], e = g_rowptr[n + 1];
    float4 a0 = make_float4(0.f, 0.f, 0.f, 0.f), a1 = a0, a2 = a0, a3 = a0;
    int i = s;
    for (; i + 4 <= e; i += 4) {
        int c0 = g_col[i], c1 = g_col[i + 1], c2 = g_col[i + 2], c3 = g_col[i + 3];
        float4 v0 = *(const float4*)&in[(size_t)c0 * 128 + lane * 4];
        float4 v1 = *(const float4*)&in[(size_t)c1 * 128 + lane * 4];
        float4 v2 = *(const float4*)&in[(size_t)c2 * 128 + lane * 4];
        float4 v3 = *(const float4*)&in[(size_t)c3 * 128 + lane * 4];
        a0.x += v0.x; a0.y += v0.y; a0.z += v0.z; a0.w += v0.w;
        a1.x += v1.x; a1.y += v1.y; a1.z += v1.z; a1.w += v1.w;
        a2.x += v2.x; a2.y += v2.y; a2.z += v2.z; a2.w += v2.w;
        a3.x += v3.x; a3.y += v3.y; a3.z += v3.z; a3.w += v3.w;
    }
    for (; i < e; i++) {
        int c = g_col[i];
        float4 v = *(const float4*)&in[(size_t)c * 128 + lane * 4];
        a0.x += v.x; a0.y += v.y; a0.z += v.z; a0.w += v.w;
    }
    float inv = g_invdeg[n];
    r.x = (a0.x + a1.x + a2.x + a3.x) * inv;
    r.y = (a0.y + a1.y + a2.y + a3.y) * inv;
    r.z = (a0.z + a1.z + a2.z + a3.z) * inv;
    r.w = (a0.w + a1.w + a2.w + a3.w) * inv;
}

__global__ void k_agg(const float* __restrict__ in, float* __restrict__ out, int relu) {
    int n = blockIdx.x * 8 + (threadIdx.x >> 5);
    if (n >= N_NODES) return;
    int lane = threadIdx.x & 31;
    float4 r;
    agg_node(in, n, lane, r);
    if (relu) {
        r.x = fmaxf(r.x, 0.f); r.y = fmaxf(r.y, 0.f);
        r.z = fmaxf(r.z, 0.f); r.w = fmaxf(r.w, 0.f);
    }
    *(float4*)&out[(size_t)n * 128 + lane * 4] = r;
}

// target-chain first agg, restricted to in-neighbors of target nodes
__global__ void k_agg_tflagged(const float* __restrict__ in, float* __restrict__ out) {
    int n = blockIdx.x * 8 + (threadIdx.x >> 5);
    if (n >= N_NODES) return;
    if (!g_tflag[n]) return;
    int lane = threadIdx.x & 31;
    float4 r;
    agg_node(in, n, lane, r);
    r.x = fmaxf(r.x, 0.f); r.y = fmaxf(r.y, 0.f);
    r.z = fmaxf(r.z, 0.f); r.w = fmaxf(r.w, 0.f);
    *(float4*)&out[(size_t)n * 128 + lane * 4] = r;
}

__global__ void k_agg_flagged(const float* __restrict__ in, float* __restrict__ out) {
    int n = blockIdx.x * 8 + (threadIdx.x >> 5);
    if (n >= N_NODES) return;
    if (!g_flag[n]) return;
    int lane = threadIdx.x & 31;
    float4 r;
    agg_node(in, n, lane, r);
    *(float4*)&out[(size_t)n * 128 + lane * 4] = r;
}

__global__ void k_agg_target(const float* __restrict__ in, const int* __restrict__ tgt,
                             float* __restrict__ out) {
    int b = blockIdx.x * 8 + (threadIdx.x >> 5);
    if (b >= T_NODES) return;
    int lane = threadIdx.x & 31;
    int n = tgt[b];
    float4 r;
    agg_node(in, n, lane, r);
    *(float4*)&out[(size_t)b * 128 + lane * 4] = r;
}

// ---------------- fused predictor (tf32 MMA, both layers, hidden stays in smem) -----
// stage 1: hid[64,256] = relu(feats[64,136] @ W + zb)   (tf32-converted into smem)
// stage 2: out[64,128] = (hid @ Wp2 + bp2) * mask
#define FS_STR 140
#define WS_STR 264
#define HID_STR 260
#define W2_STR 136
// dynamic smem union:
//   stage 1: [0 .. 64*FS_STR) feats, [64*FS_STR .. +8*WS_STR) ws  (11072 uints)
//   stage 2: [0 .. 64*HID_STR) hid (16640 uints), [16640 .. +16*W2_STR) ws2
#define PRED_SMEM_UINTS (64 * HID_STR + 16 * W2_STR)
#define PRED_SMEM (PRED_SMEM_UINTS * 4)

__global__ void __launch_bounds__(256)
k_pred(const float* __restrict__ m, const int* __restrict__ pair_s,
       const int* __restrict__ pair_t, const int* __restrict__ tgt,
       const float* __restrict__ mask, const float* __restrict__ Wp1,
       const float* __restrict__ Wp2, const float* __restrict__ bp2,
       float* __restrict__ out) {
    extern __shared__ unsigned sm[];
    int r0 = blockIdx.x * 64;
    int tid = threadIdx.x;
    __shared__ float ms[64];
    if (tid < 64) ms[tid] = mask[r0 + tid];
    int any = __syncthreads_or(tid < 64 && mask[r0 + tid] != 0.f);
    if (!any) {
        float4 zero = make_float4(0.f, 0.f, 0.f, 0.f);
#pragma unroll
        for (int i = 0; i < 8; i++) {
            int idx = tid + i * 256;
            *(float4*)&out[(size_t)r0 * 128 + idx * 4] = zero;
        }
        return;
    }

    unsigned* feats = sm;                   // stage 1 only
    unsigned* ws    = sm + 64 * FS_STR;     // stage 1 only
    unsigned* hid   = sm;                   // stage 2 (overwrites stage-1 region)
    unsigned* ws2   = sm + 64 * HID_STR;    // stage 2 weight chunk

    int lane = tid & 31, wid = tid >> 5;
    int wm = wid & 1, wn = wid >> 1;
    int gid = lane >> 2, tig = lane & 3;

    // ---------- stage 1: feats staging ----------
#pragma unroll
    for (int i = 0; i < 8; i++) {
        int idx = tid + i * 256;
        int r = idx >> 5, q = (idx & 31) << 2;
        int sN = pair_s[r0 + r];
        float4 v = *(const float4*)&m[(size_t)sN * 128 + q];
        uint4 u = make_uint4(f2tf(v.x), f2tf(v.y), f2tf(v.z), f2tf(v.w));
        *(uint4*)&feats[r * FS_STR + q] = u;
    }
    if (tid < 64) {
        int sN = pair_s[r0 + tid];
        int tN = tgt[pair_t[r0 + tid]];
        float4 ps = *(const float4*)&g_pe[sN * 4];
        float4 pt = *(const float4*)&g_pe[tN * 4];
        *(uint4*)&feats[tid * FS_STR + 128] =
            make_uint4(f2tf(ps.x), f2tf(ps.y), f2tf(ps.z), f2tf(ps.w));
        *(uint4*)&feats[tid * FS_STR + 132] =
            make_uint4(f2tf(pt.x), f2tf(pt.y), f2tf(pt.z), f2tf(pt.w));
    }

    float c[2][8][4];
#pragma unroll
    for (int mt = 0; mt < 2; mt++)
#pragma unroll
        for (int nt = 0; nt < 8; nt++)
#pragma unroll
            for (int q = 0; q < 4; q++) c[mt][nt][q] = 0.f;

    for (int ch = 0; ch < 17; ch++) {
        {
            int kk = tid >> 5, j = (tid & 31) << 3;
            const float* src = (ch < 16) ? &g_wf[(ch * 8 + kk) * 256 + j]
                                         : &Wp1[(192 + kk) * 256 + j];
            float4 v0 = *(const float4*)src;
            float4 v1 = *(const float4*)(src + 4);
            *(uint4*)&ws[kk * WS_STR + j] =
                make_uint4(f2tf(v0.x), f2tf(v0.y), f2tf(v0.z), f2tf(v0.w));
            *(uint4*)&ws[kk * WS_STR + j + 4] =
                make_uint4(f2tf(v1.x), f2tf(v1.y), f2tf(v1.z), f2tf(v1.w));
        }
        __syncthreads();
        int kb = ch * 8;
        unsigned a[2][4], b[8][2];
#pragma unroll
        for (int mt = 0; mt < 2; mt++) {
            int r = wm * 32 + mt * 16 + gid;
            a[mt][0] = feats[r * FS_STR + kb + tig];
            a[mt][1] = feats[(r + 8) * FS_STR + kb + tig];
            a[mt][2] = feats[r * FS_STR + kb + tig + 4];
            a[mt][3] = feats[(r + 8) * FS_STR + kb + tig + 4];
        }
#pragma unroll
        for (int nt = 0; nt < 8; nt++) {
            int bc = wn * 64 + nt * 8 + gid;
            b[nt][0] = ws[tig * WS_STR + bc];
            b[nt][1] = ws[(tig + 4) * WS_STR + bc];
        }
#pragma unroll
        for (int mt = 0; mt < 2; mt++)
#pragma unroll
            for (int nt = 0; nt < 8; nt++) mma8(c[mt][nt], a[mt], b[nt]);
        __syncthreads();
    }

    // ---------- hidden -> smem (relu + zb, tf32) ----------
#pragma unroll
    for (int mt = 0; mt < 2; mt++) {
        int r = wm * 32 + mt * 16 + gid;
#pragma unroll
        for (int nt = 0; nt < 8; nt++) {
            int col = wn * 64 + nt * 8 + 2 * tig;
            float2 zbv = *(const float2*)&g_zb[col];
            uint2 u0 = make_uint2(f2tf(fmaxf(c[mt][nt][0] + zbv.x, 0.f)),
                                  f2tf(fmaxf(c[mt][nt][1] + zbv.y, 0.f)));
            uint2 u1 = make_uint2(f2tf(fmaxf(c[mt][nt][2] + zbv.x, 0.f)),
                                  f2tf(fmaxf(c[mt][nt][3] + zbv.y, 0.f)));
            *(uint2*)&hid[r * HID_STR + col] = u0;
            *(uint2*)&hid[(r + 8) * HID_STR + col] = u1;
        }
    }
    __syncthreads();

    // ---------- stage 2: hid @ Wp2 ----------
    float c2[2][4][4];
#pragma unroll
    for (int mt = 0; mt < 2; mt++)
#pragma unroll
        for (int nt = 0; nt < 4; nt++)
#pragma unroll
            for (int q = 0; q < 4; q++) c2[mt][nt][q] = 0.f;

    for (int ch = 0; ch < 16; ch++) {
        {
#pragma unroll
            for (int h = 0; h < 2; h++) {
                int kk = (tid >> 5) + h * 8;
                int j = (tid & 31) << 2;
                float4 w = *(const float4*)&Wp2[(size_t)(ch * 16 + kk) * 128 + j];
                *(uint4*)&ws2[kk * W2_STR + j] =
                    make_uint4(f2tf(w.x), f2tf(w.y), f2tf(w.z), f2tf(w.w));
            }
        }
        __syncthreads();
#pragma unroll
        for (int ks = 0; ks < 2; ks++) {
            int kb = ch * 16 + ks * 8;
            unsigned a[2][4], b[4][2];
#pragma unroll
            for (int mt = 0; mt < 2; mt++) {
                int r = wm * 32 + mt * 16 + gid;
                a[mt][0] = hid[r * HID_STR + kb + tig];
                a[mt][1] = hid[(r + 8) * HID_STR + kb + tig];
                a[mt][2] = hid[r * HID_STR + kb + tig + 4];
                a[mt][3] = hid[(r + 8) * HID_STR + kb + tig + 4];
            }
#pragma unroll
            for (int nt = 0; nt < 4; nt++) {
                int bc = wn * 32 + nt * 8 + gid;
                b[nt][0] = ws2[(ks * 8 + tig) * W2_STR + bc];
                b[nt][1] = ws2[(ks * 8 + tig + 4) * W2_STR + bc];
            }
#pragma unroll
            for (int mt = 0; mt < 2; mt++)
#pragma unroll
                for (int nt = 0; nt < 4; nt++) mma8(c2[mt][nt], a[mt], b[nt]);
        }
        __syncthreads();
    }

#pragma unroll
    for (int mt = 0; mt < 2; mt++) {
        int lr = wm * 32 + mt * 16 + gid;
        float m0v = ms[lr], m1v = ms[lr + 8];
#pragma unroll
        for (int nt = 0; nt < 4; nt++) {
            int col = wn * 32 + nt * 8 + 2 * tig;
            float2 bb = *(const float2*)&bp2[col];
            float2 v0 = make_float2((c2[mt][nt][0] + bb.x) * m0v,
                                    (c2[mt][nt][1] + bb.y) * m0v);
            float2 v1 = make_float2((c2[mt][nt][2] + bb.x) * m1v,
                                    (c2[mt][nt][3] + bb.y) * m1v);
            *(float2*)&out[(size_t)(r0 + lr) * 128 + col] = v0;
            *(float2*)&out[(size_t)(r0 + lr + 8) * 128 + col] = v1;
        }
    }
}

// ---------------- launch ----------------
extern "C" void kernel_launch(void* const* d_in, const int* in_sizes, int n_in,
                              void* d_out, int out_size) {
    const float* x            = (const float*)d_in[0];
    const float* masked_x     = (const float*)d_in[1];
    const float* pos_enc      = (const float*)d_in[2];
    const int*   edge_src     = (const int*)d_in[3];
    const int*   edge_dst     = (const int*)d_in[4];
    const int*   target_nodes = (const int*)d_in[5];
    const int*   pair_t       = (const int*)d_in[6];
    const int*   pair_s       = (const int*)d_in[7];
    const float* pair_mask    = (const float*)d_in[8];
    const float* W1t          = (const float*)d_in[9];
    const float* W2t          = (const float*)d_in[10];
    const float* W1c          = (const float*)d_in[11];
    const float* W2c          = (const float*)d_in[12];
    const float* Wpe          = (const float*)d_in[13];
    const float* z            = (const float*)d_in[14];
    const float* Wp1          = (const float*)d_in[15];
    const float* bp1          = (const float*)d_in[16];
    const float* Wp2          = (const float*)d_in[17];
    const float* bp2          = (const float*)d_in[18];
    float* out = (float*)d_out;

    float *buf1, *buf2, *tbuf;
    cudaGetSymbolAddress((void**)&buf1, g_buf1);
    cudaGetSymbolAddress((void**)&buf2, g_buf2);
    cudaGetSymbolAddress((void**)&tbuf, g_tbuf);

    cudaFuncSetAttribute(k_pred, cudaFuncAttributeMaxDynamicSharedMemorySize,
                         PRED_SMEM);

    const int TPB = 256;
    int gridN = (N_NODES + TPB - 1) / TPB;
    int gridE = (N_EDGES + TPB - 1) / TPB;
    int gridM = (N_NODES + 127) / 128;
    int gridA = (N_NODES + 7) / 8;

    // CSR build, big GEMM at launch slot 4 for the profiler window
    k_zero_cnt<<<gridN, TPB>>>();
    k_count<<<gridE, TPB>>>(edge_dst);
    k_scan<<<1, 1024>>>();
    k_gemm_tf32<<<gridM, 256>>>(x, W1t, buf2, N_NODES, 0);     // x @ W1t
    k_prep<<<gridN, TPB>>>();
    k_fill<<<gridE, TPB>>>(edge_src, edge_dst);
    k_flag<<<P_PAIRS / TPB, TPB>>>(pair_s, pair_mask);
    k_tflag<<<(T_NODES + TPB - 1) / TPB, TPB>>>(target_nodes);

    // tiny precomputes
    k_pe<<<gridN, TPB>>>(pos_enc, Wpe);
    k_zb<<<1, HP>>>(z, Wp1, bp1);
    k_wf<<<DIM, HP>>>(W2c, Wp1);

    // target GCN: h = relu(agg(xW1)) at tflag nodes only ; out_emb = agg(h)[targets] @ W2t
    k_agg_tflagged<<<gridA, 256>>>(buf2, buf1);
    k_agg_target<<<(T_NODES + 7) / 8, 256>>>(buf1, target_nodes, tbuf);
    k_gemm_tf32<<<T_NODES / 128, 256>>>(tbuf, W2t, out + (size_t)P_PAIRS * DOUT,
                                        T_NODES, 0);

    // context GCN: h_c = relu(agg(mxW1c)) ; m = agg(h_c) restricted to flagged nodes
    k_gemm_tf32<<<gridM, 256>>>(masked_x, W1c, buf2, N_NODES, 0);
    k_agg<<<gridA, 256>>>(buf2, buf1, 1);
    k_agg_flagged<<<gridA, 256>>>(buf1, buf2);   // m -> buf2

    // fused predictor MLP (64-row tiles, mask-tile skipping, hidden in smem)
    k_pred<<<P_PAIRS / 64, 256, PRED_SMEM>>>(buf2, pair_s, pair_t, target_nodes,
                                             pair_mask, Wp1, Wp2, bp2, out);
}

// round 10
// speedup vs baseline: 1.4734x; 1.0413x over previous
#include <cuda_runtime.h>
#include <cstdint>

#define N_NODES 100000
#define N_EDGES 1600000
#define DIM     128
#define T_NODES 4096
#define P_PAIRS 131072
#define HP      256
#define DOUT    128
#define ZDIM    64

// ---------------- scratch (static device globals; no allocation) ----------------
__device__ int   g_cnt[N_NODES];
__device__ int   g_rowptr[N_NODES + 1];
__device__ int   g_cursor[N_NODES];
__device__ int   g_col[N_EDGES];
__device__ float g_invdeg[N_NODES];
__device__ unsigned char g_flag[N_NODES];
__device__ unsigned char g_tflag[N_NODES];
__device__ float g_pe[N_NODES * 4];
__device__ float g_zb[HP];
__device__ float g_wf[DIM * HP];                    // W2c @ Wp1[0:128]
__device__ float g_buf1[(size_t)N_NODES * DIM];
__device__ float g_buf2[(size_t)N_NODES * DIM];
__device__ float g_tbuf[(size_t)T_NODES * DIM];

// ---------------- tf32 helpers ----------------
__device__ __forceinline__ unsigned f2tf(float f) {
    unsigned u;
    asm("cvt.rna.tf32.f32 %0, %1;" : "=r"(u) : "f"(f));
    return u;
}
__device__ __forceinline__ void mma8(float* c, const unsigned* a, const unsigned* b) {
    asm volatile(
        "mma.sync.aligned.m16n8k8.row.col.f32.tf32.tf32.f32 "
        "{%0,%1,%2,%3},{%4,%5,%6,%7},{%8,%9},{%0,%1,%2,%3};"
        : "+f"(c[0]), "+f"(c[1]), "+f"(c[2]), "+f"(c[3])
        : "r"(a[0]), "r"(a[1]), "r"(a[2]), "r"(a[3]), "r"(b[0]), "r"(b[1]));
}

// ---------------- CSR build ----------------
__global__ void k_zero_cnt() {
    int i = blockIdx.x * blockDim.x + threadIdx.x;
    if (i < N_NODES) { g_cnt[i] = 0; g_flag[i] = 0; g_tflag[i] = 0; }
}

__global__ void k_count(const int* __restrict__ dst) {
    int e = blockIdx.x * blockDim.x + threadIdx.x;
    if (e < N_EDGES) atomicAdd(&g_cnt[dst[e]], 1);
}

__global__ void k_scan() {
    __shared__ int sums[1024];
    const int CH = (N_NODES + 1024) / 1024;
    int t = threadIdx.x;
    int base = t * CH;
    int s = 0;
    for (int i = 0; i < CH; i++) {
        int idx = base + i;
        if (idx < N_NODES) s += g_cnt[idx];
    }
    sums[t] = s;
    __syncthreads();
    for (int off = 1; off < 1024; off <<= 1) {
        int v = (t >= off) ? sums[t - off] : 0;
        __syncthreads();
        sums[t] += v;
        __syncthreads();
    }
    int run = sums[t] - s;
    for (int i = 0; i < CH; i++) {
        int idx = base + i;
        if (idx <= N_NODES) g_rowptr[idx] = run;
        if (idx < N_NODES) run += g_cnt[idx];
    }
}

__global__ void k_prep() {
    int i = blockIdx.x * blockDim.x + threadIdx.x;
    if (i < N_NODES) {
        g_cursor[i] = g_rowptr[i];
        int c = g_cnt[i];
        g_invdeg[i] = 1.0f / (float)(c > 0 ? c : 1);
    }
}

__global__ void k_fill(const int* __restrict__ src, const int* __restrict__ dst) {
    int e = blockIdx.x * blockDim.x + threadIdx.x;
    if (e < N_EDGES) {
        int pos = atomicAdd(&g_cursor[dst[e]], 1);
        g_col[pos] = src[e];
    }
}

__global__ void k_flag(const int* __restrict__ pair_s, const float* __restrict__ mask) {
    int i = blockIdx.x * blockDim.x + threadIdx.x;
    if (i < P_PAIRS && mask[i] != 0.f) g_flag[pair_s[i]] = 1;
}

// mark in-neighbors of target nodes (rows of h_t actually consumed by agg_target)
__global__ void k_tflag(const int* __restrict__ tgt) {
    int b = blockIdx.x * blockDim.x + threadIdx.x;
    if (b >= T_NODES) return;
    int n = tgt[b];
    int e = g_rowptr[n + 1];
    for (int i = g_rowptr[n]; i < e; i++) g_tflag[g_col[i]] = 1;
}

// ---------------- tiny precomputes ----------------
__global__ void k_pe(const float* __restrict__ pos_enc, const float* __restrict__ Wpe) {
    int n = blockIdx.x * blockDim.x + threadIdx.x;
    if (n >= N_NODES) return;
    float4 p = *(const float4*)&pos_enc[n * 4];
#pragma unroll
    for (int i = 0; i < 4; i++) {
        g_pe[n * 4 + i] = p.x * Wpe[i * 4 + 0] + p.y * Wpe[i * 4 + 1] +
                          p.z * Wpe[i * 4 + 2] + p.w * Wpe[i * 4 + 3];
    }
}

__global__ void k_zb(const float* __restrict__ z, const float* __restrict__ Wp1,
                     const float* __restrict__ bp1) {
    int j = threadIdx.x;
    float acc = bp1[j];
    for (int i = 0; i < ZDIM; i++) acc = fmaf(z[i], Wp1[(128 + i) * HP + j], acc);
    g_zb[j] = acc;
}

__global__ void k_wf(const float* __restrict__ W2c, const float* __restrict__ Wp1) {
    int i = blockIdx.x;
    int j = threadIdx.x;
    float acc = 0.f;
    for (int d = 0; d < DIM; d++) acc = fmaf(W2c[i * DIM + d], Wp1[d * HP + j], acc);
    g_wf[i * HP + j] = acc;
}

// ---------------- tf32 GEMM (R4-proven): C[M,128] = (relu?)(A[M,128] @ B[128,128]) --
#define AS_STR 36
#define BS_STR 136
__global__ void __launch_bounds__(256)
k_gemm_tf32(const float* __restrict__ A, const float* __restrict__ B,
            float* __restrict__ C, int M, int relu) {
    __shared__ unsigned As[128 * AS_STR];
    __shared__ unsigned Bs[32 * BS_STR];
    int m0 = blockIdx.x * 128;
    int tid = threadIdx.x;
    int lane = tid & 31, wid = tid >> 5;
    int wm = wid & 3, wn = wid >> 2;      // rows wm*32, cols wn*64
    int gid = lane >> 2, tig = lane & 3;

    float c[2][8][4];
#pragma unroll
    for (int mt = 0; mt < 2; mt++)
#pragma unroll
        for (int nt = 0; nt < 8; nt++)
#pragma unroll
            for (int q = 0; q < 4; q++) c[mt][nt][q] = 0.f;

    int ar = tid >> 1, acb = (tid & 1) * 16;   // A stage: 128 rows x 32 k
    int br = tid >> 3, bcb = (tid & 7) * 16;   // B stage: 32 k x 128 cols

    for (int kc = 0; kc < 128; kc += 32) {
        {
            int grow = m0 + ar;
#pragma unroll
            for (int q = 0; q < 4; q++) {
                float4 v = (grow < M)
                    ? *(const float4*)&A[(size_t)grow * 128 + kc + acb + q * 4]
                    : make_float4(0.f, 0.f, 0.f, 0.f);
                uint4 u = make_uint4(f2tf(v.x), f2tf(v.y), f2tf(v.z), f2tf(v.w));
                *(uint4*)&As[ar * AS_STR + acb + q * 4] = u;
            }
#pragma unroll
            for (int q = 0; q < 4; q++) {
                float4 v = *(const float4*)&B[(size_t)(kc + br) * 128 + bcb + q * 4];
                uint4 u = make_uint4(f2tf(v.x), f2tf(v.y), f2tf(v.z), f2tf(v.w));
                *(uint4*)&Bs[br * BS_STR + bcb + q * 4] = u;
            }
        }
        __syncthreads();
#pragma unroll
        for (int ks = 0; ks < 4; ks++) {
            int kb = ks * 8;
            unsigned a[2][4], b[8][2];
#pragma unroll
            for (int mt = 0; mt < 2; mt++) {
                int r = wm * 32 + mt * 16 + gid;
                a[mt][0] = As[r * AS_STR + kb + tig];
                a[mt][1] = As[(r + 8) * AS_STR + kb + tig];
                a[mt][2] = As[r * AS_STR + kb + tig + 4];
                a[mt][3] = As[(r + 8) * AS_STR + kb + tig + 4];
            }
#pragma unroll
            for (int nt = 0; nt < 8; nt++) {
                int bc = wn * 64 + nt * 8 + gid;
                b[nt][0] = Bs[(kb + tig) * BS_STR + bc];
                b[nt][1] = Bs[(kb + tig + 4) * BS_STR + bc];
            }
#pragma unroll
            for (int mt = 0; mt < 2; mt++)
#pragma unroll
                for (int nt = 0; nt < 8; nt++) mma8(c[mt][nt], a[mt], b[nt]);
        }
        __syncthreads();
    }

#pragma unroll
    for (int mt = 0; mt < 2; mt++) {
        int r = m0 + wm * 32 + mt * 16 + gid;
#pragma unroll
        for (int nt = 0; nt < 8; nt++) {
            int col = wn * 64 + nt * 8 + 2 * tig;
            float2 v0 = make_float2(c[mt][nt][0], c[mt][nt][1]);
            float2 v1 = make_float2(c[mt][nt][2], c[mt][nt][3]);
            if (relu) {
                v0.x = fmaxf(v0.x, 0.f); v0.y = fmaxf(v0.y, 0.f);
                v1.x = fmaxf(v1.x, 0.f); v1.y = fmaxf(v1.y, 0.f);
            }
            if (r < M)     *(float2*)&C[(size_t)r * 128 + col] = v0;
            if (r + 8 < M) *(float2*)&C[(size_t)(r + 8) * 128 + col] = v1;
        }
    }
}

// ---------------- CSR gather-aggregation: warp per node, float4 lanes ----------------
__device__ __forceinline__ void agg_node(const float* __restrict__ in, int n, int lane,
                                         float4& r) {
    int s = g_rowptr[n], e = g_rowptr[n + 1];
    float4 a0 = make_float4(0.f, 0.f, 0.f, 0.f), a1 = a0, a2 = a0, a3 = a0;
    int i = s;
    for (; i + 4 <= e; i += 4) {
        int c0 = g_col[i], c1 = g_col[i + 1], c2 = g_col[i + 2], c3 = g_col[i + 3];
        float4 v0 = *(const float4*)&in[(size_t)c0 * 128 + lane * 4];
        float4 v1 = *(const float4*)&in[(size_t)c1 * 128 + lane * 4];
        float4 v2 = *(const float4*)&in[(size_t)c2 * 128 + lane * 4];
        float4 v3 = *(const float4*)&in[(size_t)c3 * 128 + lane * 4];
        a0.x += v0.x; a0.y += v0.y; a0.z += v0.z; a0.w += v0.w;
        a1.x += v1.x; a1.y += v1.y; a1.z += v1.z; a1.w += v1.w;
        a2.x += v2.x; a2.y += v2.y; a2.z += v2.z; a2.w += v2.w;
        a3.x += v3.x; a3.y += v3.y; a3.z += v3.z; a3.w += v3.w;
    }
    for (; i < e; i++) {
        int c = g_col[i];
        float4 v = *(const float4*)&in[(size_t)c * 128 + lane * 4];
        a0.x += v.x; a0.y += v.y; a0.z += v.z; a0.w += v.w;
    }
    float inv = g_invdeg[n];
    r.x = (a0.x + a1.x + a2.x + a3.x) * inv;
    r.y = (a0.y + a1.y + a2.y + a3.y) * inv;
    r.z = (a0.z + a1.z + a2.z + a3.z) * inv;
    r.w = (a0.w + a1.w + a2.w + a3.w) * inv;
}

__global__ void k_agg(const float* __restrict__ in, float* __restrict__ out, int relu) {
    int n = blockIdx.x * 8 + (threadIdx.x >> 5);
    if (n >= N_NODES) return;
    int lane = threadIdx.x & 31;
    float4 r;
    agg_node(in, n, lane, r);
    if (relu) {
        r.x = fmaxf(r.x, 0.f); r.y = fmaxf(r.y, 0.f);
        r.z = fmaxf(r.z, 0.f); r.w = fmaxf(r.w, 0.f);
    }
    *(float4*)&out[(size_t)n * 128 + lane * 4] = r;
}

// target-chain first agg, restricted to in-neighbors of target nodes
__global__ void k_agg_tflagged(const float* __restrict__ in, float* __restrict__ out) {
    int n = blockIdx.x * 8 + (threadIdx.x >> 5);
    if (n >= N_NODES) return;
    if (!g_tflag[n]) return;
    int lane = threadIdx.x & 31;
    float4 r;
    agg_node(in, n, lane, r);
    r.x = fmaxf(r.x, 0.f); r.y = fmaxf(r.y, 0.f);
    r.z = fmaxf(r.z, 0.f); r.w = fmaxf(r.w, 0.f);
    *(float4*)&out[(size_t)n * 128 + lane * 4] = r;
}

__global__ void k_agg_flagged(const float* __restrict__ in, float* __restrict__ out) {
    int n = blockIdx.x * 8 + (threadIdx.x >> 5);
    if (n >= N_NODES) return;
    if (!g_flag[n]) return;
    int lane = threadIdx.x & 31;
    float4 r;
    agg_node(in, n, lane, r);
    *(float4*)&out[(size_t)n * 128 + lane * 4] = r;
}

__global__ void k_agg_target(const float* __restrict__ in, const int* __restrict__ tgt,
                             float* __restrict__ out) {
    int b = blockIdx.x * 8 + (threadIdx.x >> 5);
    if (b >= T_NODES) return;
    int lane = threadIdx.x & 31;
    int n = tgt[b];
    float4 r;
    agg_node(in, n, lane, r);
    *(float4*)&out[(size_t)b * 128 + lane * 4] = r;
}

// ---------------- fused predictor (tf32 MMA, both layers, k=32 weight chunks) -------
// stage 1: hid[64,256] = relu(feats[64,136] @ W + zb)   (tf32-converted into smem)
// stage 2: out[64,128] = (hid @ Wp2 + bp2) * mask
#define FS_STR 140
#define WS_STR 264
#define HID_STR 260
#define W2_STR 136
// dynamic smem union (uints):
//   stage 1: [0 .. 64*FS_STR) feats (8960), [8960 .. +32*WS_STR) ws (8448)
//   stage 2: [0 .. 64*HID_STR) hid (16640), [16640 .. +32*W2_STR) ws2 (4352)
#define PRED_SMEM_UINTS (64 * HID_STR + 32 * W2_STR)
#define PRED_SMEM (PRED_SMEM_UINTS * 4)

__global__ void __launch_bounds__(256)
k_pred(const float* __restrict__ m, const int* __restrict__ pair_s,
       const int* __restrict__ pair_t, const int* __restrict__ tgt,
       const float* __restrict__ mask, const float* __restrict__ Wp1,
       const float* __restrict__ Wp2, const float* __restrict__ bp2,
       float* __restrict__ out) {
    extern __shared__ unsigned sm[];
    int r0 = blockIdx.x * 64;
    int tid = threadIdx.x;
    __shared__ float ms[64];
    if (tid < 64) ms[tid] = mask[r0 + tid];
    int any = __syncthreads_or(tid < 64 && mask[r0 + tid] != 0.f);
    if (!any) {
        float4 zero = make_float4(0.f, 0.f, 0.f, 0.f);
#pragma unroll
        for (int i = 0; i < 8; i++) {
            int idx = tid + i * 256;
            *(float4*)&out[(size_t)r0 * 128 + idx * 4] = zero;
        }
        return;
    }

    unsigned* feats = sm;                   // stage 1 only
    unsigned* ws    = sm + 64 * FS_STR;     // stage 1 weight chunk (32 k-rows)
    unsigned* hid   = sm;                   // stage 2 (overwrites stage-1 region)
    unsigned* ws2   = sm + 64 * HID_STR;    // stage 2 weight chunk (32 k-rows)

    int lane = tid & 31, wid = tid >> 5;
    int wm = wid & 1, wn = wid >> 1;
    int gid = lane >> 2, tig = lane & 3;

    // ---------- stage 1: feats staging ----------
#pragma unroll
    for (int i = 0; i < 8; i++) {
        int idx = tid + i * 256;
        int r = idx >> 5, q = (idx & 31) << 2;
        int sN = pair_s[r0 + r];
        float4 v = *(const float4*)&m[(size_t)sN * 128 + q];
        uint4 u = make_uint4(f2tf(v.x), f2tf(v.y), f2tf(v.z), f2tf(v.w));
        *(uint4*)&feats[r * FS_STR + q] = u;
    }
    if (tid < 64) {
        int sN = pair_s[r0 + tid];
        int tN = tgt[pair_t[r0 + tid]];
        float4 ps = *(const float4*)&g_pe[sN * 4];
        float4 pt = *(const float4*)&g_pe[tN * 4];
        *(uint4*)&feats[tid * FS_STR + 128] =
            make_uint4(f2tf(ps.x), f2tf(ps.y), f2tf(ps.z), f2tf(ps.w));
        *(uint4*)&feats[tid * FS_STR + 132] =
            make_uint4(f2tf(pt.x), f2tf(pt.y), f2tf(pt.z), f2tf(pt.w));
    }

    float c[2][8][4];
#pragma unroll
    for (int mt = 0; mt < 2; mt++)
#pragma unroll
        for (int nt = 0; nt < 8; nt++)
#pragma unroll
            for (int q = 0; q < 4; q++) c[mt][nt][q] = 0.f;

    // 5 chunks: 4 x 32 k-rows from g_wf, then 8 k-rows from Wp1[192..200)
    for (int ch = 0; ch < 5; ch++) {
        int nrows = (ch < 4) ? 32 : 8;
        {
            int kk = tid >> 3, t = tid & 7;
            if (kk < nrows) {
                const float* srcrow = (ch < 4) ? &g_wf[(size_t)(ch * 32 + kk) * 256]
                                               : &Wp1[(size_t)(192 + kk) * 256];
#pragma unroll
                for (int q = 0; q < 8; q++) {
                    int j = t * 4 + 32 * q;
                    float4 v = *(const float4*)&srcrow[j];
                    *(uint4*)&ws[kk * WS_STR + j] =
                        make_uint4(f2tf(v.x), f2tf(v.y), f2tf(v.z), f2tf(v.w));
                }
            }
        }
        __syncthreads();
        int nks = nrows >> 3;
        for (int ks = 0; ks < nks; ks++) {
            int kb = ch * 32 + ks * 8;  // absolute k into feats
            int kl = ks * 8;            // local k into ws
            unsigned a[2][4], b[8][2];
#pragma unroll
            for (int mt = 0; mt < 2; mt++) {
                int r = wm * 32 + mt * 16 + gid;
                a[mt][0] = feats[r * FS_STR + kb + tig];
                a[mt][1] = feats[(r + 8) * FS_STR + kb + tig];
                a[mt][2] = feats[r * FS_STR + kb + tig + 4];
                a[mt][3] = feats[(r + 8) * FS_STR + kb + tig + 4];
            }
#pragma unroll
            for (int nt = 0; nt < 8; nt++) {
                int bc = wn * 64 + nt * 8 + gid;
                b[nt][0] = ws[(kl + tig) * WS_STR + bc];
                b[nt][1] = ws[(kl + tig + 4) * WS_STR + bc];
            }
#pragma unroll
            for (int mt = 0; mt < 2; mt++)
#pragma unroll
                for (int nt = 0; nt < 8; nt++) mma8(c[mt][nt], a[mt], b[nt]);
        }
        __syncthreads();
    }

    // ---------- hidden -> smem (relu + zb, tf32) ----------
#pragma unroll
    for (int mt = 0; mt < 2; mt++) {
        int r = wm * 32 + mt * 16 + gid;
#pragma unroll
        for (int nt = 0; nt < 8; nt++) {
            int col = wn * 64 + nt * 8 + 2 * tig;
            float2 zbv = *(const float2*)&g_zb[col];
            uint2 u0 = make_uint2(f2tf(fmaxf(c[mt][nt][0] + zbv.x, 0.f)),
                                  f2tf(fmaxf(c[mt][nt][1] + zbv.y, 0.f)));
            uint2 u1 = make_uint2(f2tf(fmaxf(c[mt][nt][2] + zbv.x, 0.f)),
                                  f2tf(fmaxf(c[mt][nt][3] + zbv.y, 0.f)));
            *(uint2*)&hid[r * HID_STR + col] = u0;
            *(uint2*)&hid[(r + 8) * HID_STR + col] = u1;
        }
    }
    __syncthreads();

    // ---------- stage 2: hid @ Wp2, k=32 chunks ----------
    float c2[2][4][4];
#pragma unroll
    for (int mt = 0; mt < 2; mt++)
#pragma unroll
        for (int nt = 0; nt < 4; nt++)
#pragma unroll
            for (int q = 0; q < 4; q++) c2[mt][nt][q] = 0.f;

    for (int ch = 0; ch < 8; ch++) {
        {
            int kk = tid >> 3, t = tid & 7;
            const float* srcrow = &Wp2[(size_t)(ch * 32 + kk) * 128];
#pragma unroll
            for (int q = 0; q < 4; q++) {
                int j = t * 4 + 32 * q;
                float4 w = *(const float4*)&srcrow[j];
                *(uint4*)&ws2[kk * W2_STR + j] =
                    make_uint4(f2tf(w.x), f2tf(w.y), f2tf(w.z), f2tf(w.w));
            }
        }
        __syncthreads();
#pragma unroll
        for (int ks = 0; ks < 4; ks++) {
            int kb = ch * 32 + ks * 8;  // absolute k into hid
            int kl = ks * 8;            // local k into ws2
            unsigned a[2][4], b[4][2];
#pragma unroll
            for (int mt = 0; mt < 2; mt++) {
                int r = wm * 32 + mt * 16 + gid;
                a[mt][0] = hid[r * HID_STR + kb + tig];
                a[mt][1] = hid[(r + 8) * HID_STR + kb + tig];
                a[mt][2] = hid[r * HID_STR + kb + tig + 4];
                a[mt][3] = hid[(r + 8) * HID_STR + kb + tig + 4];
            }
#pragma unroll
            for (int nt = 0; nt < 4; nt++) {
                int bc = wn * 32 + nt * 8 + gid;
                b[nt][0] = ws2[(kl + tig) * W2_STR + bc];
                b[nt][1] = ws2[(kl + tig + 4) * W2_STR + bc];
            }
#pragma unroll
            for (int mt = 0; mt < 2; mt++)
#pragma unroll
                for (int nt = 0; nt < 4; nt++) mma8(c2[mt][nt], a[mt], b[nt]);
        }
        __syncthreads();
    }

#pragma unroll
    for (int mt = 0; mt < 2; mt++) {
        int lr = wm * 32 + mt * 16 + gid;
        float m0v = ms[lr], m1v = ms[lr + 8];
#pragma unroll
        for (int nt = 0; nt < 4; nt++) {
            int col = wn * 32 + nt * 8 + 2 * tig;
            float2 bb = *(const float2*)&bp2[col];
            float2 v0 = make_float2((c2[mt][nt][0] + bb.x) * m0v,
                                    (c2[mt][nt][1] + bb.y) * m0v);
            float2 v1 = make_float2((c2[mt][nt][2] + bb.x) * m1v,
                                    (c2[mt][nt][3] + bb.y) * m1v);
            *(float2*)&out[(size_t)(r0 + lr) * 128 + col] = v0;
            *(float2*)&out[(size_t)(r0 + lr + 8) * 128 + col] = v1;
        }
    }
}

// ---------------- launch ----------------
extern "C" void kernel_launch(void* const* d_in, const int* in_sizes, int n_in,
                              void* d_out, int out_size) {
    const float* x            = (const float*)d_in[0];
    const float* masked_x     = (const float*)d_in[1];
    const float* pos_enc      = (const float*)d_in[2];
    const int*   edge_src     = (const int*)d_in[3];
    const int*   edge_dst     = (const int*)d_in[4];
    const int*   target_nodes = (const int*)d_in[5];
    const int*   pair_t       = (const int*)d_in[6];
    const int*   pair_s       = (const int*)d_in[7];
    const float* pair_mask    = (const float*)d_in[8];
    const float* W1t          = (const float*)d_in[9];
    const float* W2t          = (const float*)d_in[10];
    const float* W1c          = (const float*)d_in[11];
    const float* W2c          = (const float*)d_in[12];
    const float* Wpe          = (const float*)d_in[13];
    const float* z            = (const float*)d_in[14];
    const float* Wp1          = (const float*)d_in[15];
    const float* bp1          = (const float*)d_in[16];
    const float* Wp2          = (const float*)d_in[17];
    const float* bp2          = (const float*)d_in[18];
    float* out = (float*)d_out;

    float *buf1, *buf2, *tbuf;
    cudaGetSymbolAddress((void**)&buf1, g_buf1);
    cudaGetSymbolAddress((void**)&buf2, g_buf2);
    cudaGetSymbolAddress((void**)&tbuf, g_tbuf);

    cudaFuncSetAttribute(k_pred, cudaFuncAttributeMaxDynamicSharedMemorySize,
                         PRED_SMEM);

    const int TPB = 256;
    int gridN = (N_NODES + TPB - 1) / TPB;
    int gridE = (N_EDGES + TPB - 1) / TPB;
    int gridM = (N_NODES + 127) / 128;
    int gridA = (N_NODES + 7) / 8;

    // CSR build, big GEMM at launch slot 4 for the profiler window
    k_zero_cnt<<<gridN, TPB>>>();
    k_count<<<gridE, TPB>>>(edge_dst);
    k_scan<<<1, 1024>>>();
    k_gemm_tf32<<<gridM, 256>>>(x, W1t, buf2, N_NODES, 0);     // x @ W1t
    k_prep<<<gridN, TPB>>>();
    k_fill<<<gridE, TPB>>>(edge_src, edge_dst);
    k_flag<<<P_PAIRS / TPB, TPB>>>(pair_s, pair_mask);
    k_tflag<<<(T_NODES + TPB - 1) / TPB, TPB>>>(target_nodes);

    // tiny precomputes
    k_pe<<<gridN, TPB>>>(pos_enc, Wpe);
    k_zb<<<1, HP>>>(z, Wp1, bp1);
    k_wf<<<DIM, HP>>>(W2c, Wp1);

    // target GCN: h = relu(agg(xW1)) at tflag nodes only ; out_emb = agg(h)[targets] @ W2t
    k_agg_tflagged<<<gridA, 256>>>(buf2, buf1);
    k_agg_target<<<(T_NODES + 7) / 8, 256>>>(buf1, target_nodes, tbuf);
    k_gemm_tf32<<<T_NODES / 128, 256>>>(tbuf, W2t, out + (size_t)P_PAIRS * DOUT,
                                        T_NODES, 0);

    // context GCN: h_c = relu(agg(mxW1c)) ; m = agg(h_c) restricted to flagged nodes
    k_gemm_tf32<<<gridM, 256>>>(masked_x, W1c, buf2, N_NODES, 0);
    k_agg<<<gridA, 256>>>(buf2, buf1, 1);
    k_agg_flagged<<<gridA, 256>>>(buf1, buf2);   // m -> buf2

    // fused predictor MLP (64-row tiles, mask-tile skipping, k=32 weight chunks)
    k_pred<<<P_PAIRS / 64, 256, PRED_SMEM>>>(buf2, pair_s, pair_t, target_nodes,
                                             pair_mask, Wp1, Wp2, bp2, out);
}

// round 11
// speedup vs baseline: 1.5365x; 1.0428x over previous
#include <cuda_runtime.h>
#include <cstdint>

#define N_NODES 100000
#define N_EDGES 1600000
#define DIM     128
#define T_NODES 4096
#define P_PAIRS 131072
#define HP      256
#define DOUT    128
#define ZDIM    64

// ---------------- scratch (static device globals; no allocation) ----------------
__device__ int   g_cnt[N_NODES];
__device__ int   g_rowptr[N_NODES + 1];
__device__ int   g_cursor[N_NODES];
__device__ int   g_col[N_EDGES];
__device__ float g_invdeg[N_NODES];
__device__ unsigned char g_flag[N_NODES];
__device__ unsigned char g_tflag[N_NODES];
__device__ float g_pe[N_NODES * 4];
__device__ float g_zb[HP];
__device__ float g_wf[DIM * HP];                    // W2c @ Wp1[0:128]
__device__ float g_buf1[(size_t)N_NODES * DIM];
__device__ float g_buf2[(size_t)N_NODES * DIM];
__device__ float g_tbuf[(size_t)T_NODES * DIM];

// ---------------- tf32 / mma helpers ----------------
__device__ __forceinline__ unsigned f2tf(float f) {
    unsigned u;
    asm("cvt.rna.tf32.f32 %0, %1;" : "=r"(u) : "f"(f));
    return u;
}
__device__ __forceinline__ void mma8(float* c, const unsigned* a, const unsigned* b) {
    asm volatile(
        "mma.sync.aligned.m16n8k8.row.col.f32.tf32.tf32.f32 "
        "{%0,%1,%2,%3},{%4,%5,%6,%7},{%8,%9},{%0,%1,%2,%3};"
        : "+f"(c[0]), "+f"(c[1]), "+f"(c[2]), "+f"(c[3])
        : "r"(a[0]), "r"(a[1]), "r"(a[2]), "r"(a[3]), "r"(b[0]), "r"(b[1]));
}
__device__ __forceinline__ void ldsm4(unsigned* r, const unsigned* p) {
    unsigned addr = (unsigned)__cvta_generic_to_shared(p);
    asm volatile("ldmatrix.sync.aligned.m8n8.x4.shared.b16 {%0,%1,%2,%3}, [%4];"
                 : "=r"(r[0]), "=r"(r[1]), "=r"(r[2]), "=r"(r[3]) : "r"(addr));
}

// ---------------- CSR build ----------------
__global__ void k_zero_cnt() {
    int i = blockIdx.x * blockDim.x + threadIdx.x;
    if (i < N_NODES) { g_cnt[i] = 0; g_flag[i] = 0; g_tflag[i] = 0; }
}

__global__ void k_count(const int* __restrict__ dst) {
    int e = blockIdx.x * blockDim.x + threadIdx.x;
    if (e < N_EDGES) atomicAdd(&g_cnt[dst[e]], 1);
}

__global__ void k_scan() {
    __shared__ int sums[1024];
    const int CH = (N_NODES + 1024) / 1024;
    int t = threadIdx.x;
    int base = t * CH;
    int s = 0;
    for (int i = 0; i < CH; i++) {
        int idx = base + i;
        if (idx < N_NODES) s += g_cnt[idx];
    }
    sums[t] = s;
    __syncthreads();
    for (int off = 1; off < 1024; off <<= 1) {
        int v = (t >= off) ? sums[t - off] : 0;
        __syncthreads();
        sums[t] += v;
        __syncthreads();
    }
    int run = sums[t] - s;
    for (int i = 0; i < CH; i++) {
        int idx = base + i;
        if (idx <= N_NODES) g_rowptr[idx] = run;
        if (idx < N_NODES) run += g_cnt[idx];
    }
}

__global__ void k_prep() {
    int i = blockIdx.x * blockDim.x + threadIdx.x;
    if (i < N_NODES) {
        g_cursor[i] = g_rowptr[i];
        int c = g_cnt[i];
        g_invdeg[i] = 1.0f / (float)(c > 0 ? c : 1);
    }
}

__global__ void k_fill(const int* __restrict__ src, const int* __restrict__ dst) {
    int e = blockIdx.x * blockDim.x + threadIdx.x;
    if (e < N_EDGES) {
        int pos = atomicAdd(&g_cursor[dst[e]], 1);
        g_col[pos] = src[e];
    }
}

__global__ void k_flag(const int* __restrict__ pair_s, const float* __restrict__ mask) {
    int i = blockIdx.x * blockDim.x + threadIdx.x;
    if (i < P_PAIRS && mask[i] != 0.f) g_flag[pair_s[i]] = 1;
}

// mark in-neighbors of target nodes (rows of h_t actually consumed by agg_target)
__global__ void k_tflag(const int* __restrict__ tgt) {
    int b = blockIdx.x * blockDim.x + threadIdx.x;
    if (b >= T_NODES) return;
    int n = tgt[b];
    int e = g_rowptr[n + 1];
    for (int i = g_rowptr[n]; i < e; i++) g_tflag[g_col[i]] = 1;
}

// ---------------- tiny precomputes ----------------
__global__ void k_pe(const float* __restrict__ pos_enc, const float* __restrict__ Wpe) {
    int n = blockIdx.x * blockDim.x + threadIdx.x;
    if (n >= N_NODES) return;
    float4 p = *(const float4*)&pos_enc[n * 4];
#pragma unroll
    for (int i = 0; i < 4; i++) {
        g_pe[n * 4 + i] = p.x * Wpe[i * 4 + 0] + p.y * Wpe[i * 4 + 1] +
                          p.z * Wpe[i * 4 + 2] + p.w * Wpe[i * 4 + 3];
    }
}

__global__ void k_zb(const float* __restrict__ z, const float* __restrict__ Wp1,
                     const float* __restrict__ bp1) {
    int j = threadIdx.x;
    float acc = bp1[j];
    for (int i = 0; i < ZDIM; i++) acc = fmaf(z[i], Wp1[(128 + i) * HP + j], acc);
    g_zb[j] = acc;
}

__global__ void k_wf(const float* __restrict__ W2c, const float* __restrict__ Wp1) {
    int i = blockIdx.x;
    int j = threadIdx.x;
    float acc = 0.f;
    for (int d = 0; d < DIM; d++) acc = fmaf(W2c[i * DIM + d], Wp1[d * HP + j], acc);
    g_wf[i * HP + j] = acc;
}

// ---------------- tf32 GEMM: C[M,128] = (relu?)(A[M,128] @ B[128,128]) -------------
// 128x128 block, 256 threads (8 warps 4m x 2n), per-chunk staging (k=32).
// A staged [row][k_local] stride 36; B staged TRANSPOSED [n][k_local] stride 36.
// Fragments via ldmatrix.x4 (b16 trick: one 8x8 b16 matrix == 8x4 tf32 block;
// lane L of matrix m receives tf32 element [L/4][L%4] -> exact mma fragment map).
#define AS_STR 36
#define BT_STR 36
__global__ void __launch_bounds__(256)
k_gemm_tf32(const float* __restrict__ A, const float* __restrict__ B,
            float* __restrict__ C, int M, int relu) {
    __shared__ unsigned As[128 * AS_STR];
    __shared__ unsigned Bst[128 * BT_STR];
    int m0 = blockIdx.x * 128;
    int tid = threadIdx.x;
    int lane = tid & 31, wid = tid >> 5;
    int wm = wid & 3, wn = wid >> 2;      // rows wm*32, cols wn*64
    int gid = lane >> 2, tig = lane & 3;

    float c[2][8][4];
#pragma unroll
    for (int mt = 0; mt < 2; mt++)
#pragma unroll
        for (int nt = 0; nt < 8; nt++)
#pragma unroll
            for (int q = 0; q < 4; q++) c[mt][nt][q] = 0.f;

    int ar = tid >> 1, acb = (tid & 1) * 16;   // A stage: 128 rows x 32 k
    int bn = tid & 127, bkh = (tid >> 7) * 16; // B stage: 128 n x 32 k (transposed)

    // ldmatrix fragment base pointers (within per-chunk tiles)
    const unsigned* pa0 = &As[(wm * 32 + (lane & 15)) * AS_STR + ((lane >> 4) << 2)];
    const unsigned* pa1 = pa0 + 16 * AS_STR;
    const unsigned* pb  = &Bst[(wn * 64 + ((lane >> 4) << 3) + (lane & 7)) * BT_STR +
                               (((lane >> 3) & 1) << 2)];

    for (int kc = 0; kc < 128; kc += 32) {
        {
            int grow = m0 + ar;
#pragma unroll
            for (int q = 0; q < 2; q++) {
                float4 v0 = (grow < M)
                    ? *(const float4*)&A[(size_t)grow * 128 + kc + acb + q * 8]
                    : make_float4(0.f, 0.f, 0.f, 0.f);
                float4 v1 = (grow < M)
                    ? *(const float4*)&A[(size_t)grow * 128 + kc + acb + q * 8 + 4]
                    : make_float4(0.f, 0.f, 0.f, 0.f);
                *(uint4*)&As[ar * AS_STR + acb + q * 8] =
                    make_uint4(f2tf(v0.x), f2tf(v0.y), f2tf(v0.z), f2tf(v0.w));
                *(uint4*)&As[ar * AS_STR + acb + q * 8 + 4] =
                    make_uint4(f2tf(v1.x), f2tf(v1.y), f2tf(v1.z), f2tf(v1.w));
            }
            // B transposed staging: 4 uint4 per thread, coalesced across n per k-row
#pragma unroll
            for (int q = 0; q < 4; q++) {
                int kk = bkh + q * 4;
                uint4 u;
                u.x = f2tf(B[(size_t)(kc + kk + 0) * 128 + bn]);
                u.y = f2tf(B[(size_t)(kc + kk + 1) * 128 + bn]);
                u.z = f2tf(B[(size_t)(kc + kk + 2) * 128 + bn]);
                u.w = f2tf(B[(size_t)(kc + kk + 3) * 128 + bn]);
                *(uint4*)&Bst[bn * BT_STR + kk] = u;
            }
        }
        __syncthreads();
#pragma unroll
        for (int ks = 0; ks < 4; ks++) {
            int kb = ks * 8;
            unsigned a[2][4], b[8][2];
            ldsm4(a[0], pa0 + kb);
            ldsm4(a[1], pa1 + kb);
#pragma unroll
            for (int p = 0; p < 4; p++) {
                unsigned t4[4];
                ldsm4(t4, pb + p * 16 * BT_STR + kb);
                b[2 * p][0] = t4[0]; b[2 * p][1] = t4[1];
                b[2 * p + 1][0] = t4[2]; b[2 * p + 1][1] = t4[3];
            }
#pragma unroll
            for (int mt = 0; mt < 2; mt++)
#pragma unroll
                for (int nt = 0; nt < 8; nt++) mma8(c[mt][nt], a[mt], b[nt]);
        }
        __syncthreads();
    }

#pragma unroll
    for (int mt = 0; mt < 2; mt++) {
        int r = m0 + wm * 32 + mt * 16 + gid;
#pragma unroll
        for (int nt = 0; nt < 8; nt++) {
            int col = wn * 64 + nt * 8 + 2 * tig;
            float2 v0 = make_float2(c[mt][nt][0], c[mt][nt][1]);
            float2 v1 = make_float2(c[mt][nt][2], c[mt][nt][3]);
            if (relu) {
                v0.x = fmaxf(v0.x, 0.f); v0.y = fmaxf(v0.y, 0.f);
                v1.x = fmaxf(v1.x, 0.f); v1.y = fmaxf(v1.y, 0.f);
            }
            if (r < M)     *(float2*)&C[(size_t)r * 128 + col] = v0;
            if (r + 8 < M) *(float2*)&C[(size_t)(r + 8) * 128 + col] = v1;
        }
    }
}

// ---------------- CSR gather-aggregation: warp per node, float4 lanes ----------------
__device__ __forceinline__ void agg_node(const float* __restrict__ in, int n, int lane,
                                         float4& r) {
    int s = g_rowptr[n], e = g_rowptr[n + 1];
    float4 a0 = make_float4(0.f, 0.f, 0.f, 0.f), a1 = a0, a2 = a0, a3 = a0;
    int i = s;
    for (; i + 4 <= e; i += 4) {
        int c0 = g_col[i], c1 = g_col[i + 1], c2 = g_col[i + 2], c3 = g_col[i + 3];
        float4 v0 = *(const float4*)&in[(size_t)c0 * 128 + lane * 4];
        float4 v1 = *(const float4*)&in[(size_t)c1 * 128 + lane * 4];
        float4 v2 = *(const float4*)&in[(size_t)c2 * 128 + lane * 4];
        float4 v3 = *(const float4*)&in[(size_t)c3 * 128 + lane * 4];
        a0.x += v0.x; a0.y += v0.y; a0.z += v0.z; a0.w += v0.w;
        a1.x += v1.x; a1.y += v1.y; a1.z += v1.z; a1.w += v1.w;
        a2.x += v2.x; a2.y += v2.y; a2.z += v2.z; a2.w += v2.w;
        a3.x += v3.x; a3.y += v3.y; a3.z += v3.z; a3.w += v3.w;
    }
    for (; i < e; i++) {
        int c = g_col[i];
        float4 v = *(const float4*)&in[(size_t)c * 128 + lane * 4];
        a0.x += v.x; a0.y += v.y; a0.z += v.z; a0.w += v.w;
    }
    float inv = g_invdeg[n];
    r.x = (a0.x + a1.x + a2.x + a3.x) * inv;
    r.y = (a0.y + a1.y + a2.y + a3.y) * inv;
    r.z = (a0.z + a1.z + a2.z + a3.z) * inv;
    r.w = (a0.w + a1.w + a2.w + a3.w) * inv;
}

__global__ void k_agg(const float* __restrict__ in, float* __restrict__ out, int relu) {
    int n = blockIdx.x * 8 + (threadIdx.x >> 5);
    if (n >= N_NODES) return;
    int lane = threadIdx.x & 31;
    float4 r;
    agg_node(in, n, lane, r);
    if (relu) {
        r.x = fmaxf(r.x, 0.f); r.y = fmaxf(r.y, 0.f);
        r.z = fmaxf(r.z, 0.f); r.w = fmaxf(r.w, 0.f);
    }
    *(float4*)&out[(size_t)n * 128 + lane * 4] = r;
}

// target-chain first agg, restricted to in-neighbors of target nodes
__global__ void k_agg_tflagged(const float* __restrict__ in, float* __restrict__ out) {
    int n = blockIdx.x * 8 + (threadIdx.x >> 5);
    if (n >= N_NODES) return;
    if (!g_tflag[n]) return;
    int lane = threadIdx.x & 31;
    float4 r;
    agg_node(in, n, lane, r);
    r.x = fmaxf(r.x, 0.f); r.y = fmaxf(r.y, 0.f);
    r.z = fmaxf(r.z, 0.f); r.w = fmaxf(r.w, 0.f);
    *(float4*)&out[(size_t)n * 128 + lane * 4] = r;
}

__global__ void k_agg_flagged(const float* __restrict__ in, float* __restrict__ out) {
    int n = blockIdx.x * 8 + (threadIdx.x >> 5);
    if (n >= N_NODES) return;
    if (!g_flag[n]) return;
    int lane = threadIdx.x & 31;
    float4 r;
    agg_node(in, n, lane, r);
    *(float4*)&out[(size_t)n * 128 + lane * 4] = r;
}

__global__ void k_agg_target(const float* __restrict__ in, const int* __restrict__ tgt,
                             float* __restrict__ out) {
    int b = blockIdx.x * 8 + (threadIdx.x >> 5);
    if (b >= T_NODES) return;
    int lane = threadIdx.x & 31;
    int n = tgt[b];
    float4 r;
    agg_node(in, n, lane, r);
    *(float4*)&out[(size_t)b * 128 + lane * 4] = r;
}

// ---------------- fused predictor (tf32 MMA, both layers, k=32 weight chunks) -------
// stage 1: hid[64,256] = relu(feats[64,136] @ W + zb)   (tf32-converted into smem)
// stage 2: out[64,128] = (hid @ Wp2 + bp2) * mask
#define FS_STR 140
#define WS_STR 264
#define HID_STR 260
#define W2_STR 136
#define PRED_SMEM_UINTS (64 * HID_STR + 32 * W2_STR)
#define PRED_SMEM (PRED_SMEM_UINTS * 4)

__global__ void __launch_bounds__(256)
k_pred(const float* __restrict__ m, const int* __restrict__ pair_s,
       const int* __restrict__ pair_t, const int* __restrict__ tgt,
       const float* __restrict__ mask, const float* __restrict__ Wp1,
       const float* __restrict__ Wp2, const float* __restrict__ bp2,
       float* __restrict__ out) {
    extern __shared__ unsigned sm[];
    int r0 = blockIdx.x * 64;
    int tid = threadIdx.x;
    __shared__ float ms[64];
    if (tid < 64) ms[tid] = mask[r0 + tid];
    int any = __syncthreads_or(tid < 64 && mask[r0 + tid] != 0.f);
    if (!any) {
        float4 zero = make_float4(0.f, 0.f, 0.f, 0.f);
#pragma unroll
        for (int i = 0; i < 8; i++) {
            int idx = tid + i * 256;
            *(float4*)&out[(size_t)r0 * 128 + idx * 4] = zero;
        }
        return;
    }

    unsigned* feats = sm;                   // stage 1 only
    unsigned* ws    = sm + 64 * FS_STR;     // stage 1 weight chunk (32 k-rows)
    unsigned* hid   = sm;                   // stage 2 (overwrites stage-1 region)
    unsigned* ws2   = sm + 64 * HID_STR;    // stage 2 weight chunk (32 k-rows)

    int lane = tid & 31, wid = tid >> 5;
    int wm = wid & 1, wn = wid >> 1;
    int gid = lane >> 2, tig = lane & 3;

    // ---------- stage 1: feats staging ----------
#pragma unroll
    for (int i = 0; i < 8; i++) {
        int idx = tid + i * 256;
        int r = idx >> 5, q = (idx & 31) << 2;
        int sN = pair_s[r0 + r];
        float4 v = *(const float4*)&m[(size_t)sN * 128 + q];
        uint4 u = make_uint4(f2tf(v.x), f2tf(v.y), f2tf(v.z), f2tf(v.w));
        *(uint4*)&feats[r * FS_STR + q] = u;
    }
    if (tid < 64) {
        int sN = pair_s[r0 + tid];
        int tN = tgt[pair_t[r0 + tid]];
        float4 ps = *(const float4*)&g_pe[sN * 4];
        float4 pt = *(const float4*)&g_pe[tN * 4];
        *(uint4*)&feats[tid * FS_STR + 128] =
            make_uint4(f2tf(ps.x), f2tf(ps.y), f2tf(ps.z), f2tf(ps.w));
        *(uint4*)&feats[tid * FS_STR + 132] =
            make_uint4(f2tf(pt.x), f2tf(pt.y), f2tf(pt.z), f2tf(pt.w));
    }

    float c[2][8][4];
#pragma unroll
    for (int mt = 0; mt < 2; mt++)
#pragma unroll
        for (int nt = 0; nt < 8; nt++)
#pragma unroll
            for (int q = 0; q < 4; q++) c[mt][nt][q] = 0.f;

    // 5 chunks: 4 x 32 k-rows from g_wf, then 8 k-rows from Wp1[192..200)
    for (int ch = 0; ch < 5; ch++) {
        int nrows = (ch < 4) ? 32 : 8;
        {
            int kk = tid >> 3, t = tid & 7;
            if (kk < nrows) {
                const float* srcrow = (ch < 4) ? &g_wf[(size_t)(ch * 32 + kk) * 256]
                                               : &Wp1[(size_t)(192 + kk) * 256];
#pragma unroll
                for (int q = 0; q < 8; q++) {
                    int j = t * 4 + 32 * q;
                    float4 v = *(const float4*)&srcrow[j];
                    *(uint4*)&ws[kk * WS_STR + j] =
                        make_uint4(f2tf(v.x), f2tf(v.y), f2tf(v.z), f2tf(v.w));
                }
            }
        }
        __syncthreads();
        int nks = nrows >> 3;
        for (int ks = 0; ks < nks; ks++) {
            int kb = ch * 32 + ks * 8;  // absolute k into feats
            int kl = ks * 8;            // local k into ws
            unsigned a[2][4], b[8][2];
#pragma unroll
            for (int mt = 0; mt < 2; mt++) {
                int r = wm * 32 + mt * 16 + gid;
                a[mt][0] = feats[r * FS_STR + kb + tig];
                a[mt][1] = feats[(r + 8) * FS_STR + kb + tig];
                a[mt][2] = feats[r * FS_STR + kb + tig + 4];
                a[mt][3] = feats[(r + 8) * FS_STR + kb + tig + 4];
            }
#pragma unroll
            for (int nt = 0; nt < 8; nt++) {
                int bc = wn * 64 + nt * 8 + gid;
                b[nt][0] = ws[(kl + tig) * WS_STR + bc];
                b[nt][1] = ws[(kl + tig + 4) * WS_STR + bc];
            }
#pragma unroll
            for (int mt = 0; mt < 2; mt++)
#pragma unroll
                for (int nt = 0; nt < 8; nt++) mma8(c[mt][nt], a[mt], b[nt]);
        }
        __syncthreads();
    }

    // ---------- hidden -> smem (relu + zb, tf32) ----------
#pragma unroll
    for (int mt = 0; mt < 2; mt++) {
        int r = wm * 32 + mt * 16 + gid;
#pragma unroll
        for (int nt = 0; nt < 8; nt++) {
            int col = wn * 64 + nt * 8 + 2 * tig;
            float2 zbv = *(const float2*)&g_zb[col];
            uint2 u0 = make_uint2(f2tf(fmaxf(c[mt][nt][0] + zbv.x, 0.f)),
                                  f2tf(fmaxf(c[mt][nt][1] + zbv.y, 0.f)));
            uint2 u1 = make_uint2(f2tf(fmaxf(c[mt][nt][2] + zbv.x, 0.f)),
                                  f2tf(fmaxf(c[mt][nt][3] + zbv.y, 0.f)));
            *(uint2*)&hid[r * HID_STR + col] = u0;
            *(uint2*)&hid[(r + 8) * HID_STR + col] = u1;
        }
    }
    __syncthreads();

    // ---------- stage 2: hid @ Wp2, k=32 chunks ----------
    float c2[2][4][4];
#pragma unroll
    for (int mt = 0; mt < 2; mt++)
#pragma unroll
        for (int nt = 0; nt < 4; nt++)
#pragma unroll
            for (int q = 0; q < 4; q++) c2[mt][nt][q] = 0.f;

    for (int ch = 0; ch < 8; ch++) {
        {
            int kk = tid >> 3, t = tid & 7;
            const float* srcrow = &Wp2[(size_t)(ch * 32 + kk) * 128];
#pragma unroll
            for (int q = 0; q < 4; q++) {
                int j = t * 4 + 32 * q;
                float4 w = *(const float4*)&srcrow[j];
                *(uint4*)&ws2[kk * W2_STR + j] =
                    make_uint4(f2tf(w.x), f2tf(w.y), f2tf(w.z), f2tf(w.w));
            }
        }
        __syncthreads();
#pragma unroll
        for (int ks = 0; ks < 4; ks++) {
            int kb = ch * 32 + ks * 8;  // absolute k into hid
            int kl = ks * 8;            // local k into ws2
            unsigned a[2][4], b[4][2];
#pragma unroll
            for (int mt = 0; mt < 2; mt++) {
                int r = wm * 32 + mt * 16 + gid;
                a[mt][0] = hid[r * HID_STR + kb + tig];
                a[mt][1] = hid[(r + 8) * HID_STR + kb + tig];
                a[mt][2] = hid[r * HID_STR + kb + tig + 4];
                a[mt][3] = hid[(r + 8) * HID_STR + kb + tig + 4];
            }
#pragma unroll
            for (int nt = 0; nt < 4; nt++) {
                int bc = wn * 32 + nt * 8 + gid;
                b[nt][0] = ws2[(kl + tig) * W2_STR + bc];
                b[nt][1] = ws2[(kl + tig + 4) * W2_STR + bc];
            }
#pragma unroll
            for (int mt = 0; mt < 2; mt++)
#pragma unroll
                for (int nt = 0; nt < 4; nt++) mma8(c2[mt][nt], a[mt], b[nt]);
        }
        __syncthreads();
    }

#pragma unroll
    for (int mt = 0; mt < 2; mt++) {
        int lr = wm * 32 + mt * 16 + gid;
        float m0v = ms[lr], m1v = ms[lr + 8];
#pragma unroll
        for (int nt = 0; nt < 4; nt++) {
            int col = wn * 32 + nt * 8 + 2 * tig;
            float2 bb = *(const float2*)&bp2[col];
            float2 v0 = make_float2((c2[mt][nt][0] + bb.x) * m0v,
                                    (c2[mt][nt][1] + bb.y) * m0v);
            float2 v1 = make_float2((c2[mt][nt][2] + bb.x) * m1v,
                                    (c2[mt][nt][3] + bb.y) * m1v);
            *(float2*)&out[(size_t)(r0 + lr) * 128 + col] = v0;
            *(float2*)&out[(size_t)(r0 + lr + 8) * 128 + col] = v1;
        }
    }
}

// ---------------- launch ----------------
extern "C" void kernel_launch(void* const* d_in, const int* in_sizes, int n_in,
                              void* d_out, int out_size) {
    const float* x            = (const float*)d_in[0];
    const float* masked_x     = (const float*)d_in[1];
    const float* pos_enc      = (const float*)d_in[2];
    const int*   edge_src     = (const int*)d_in[3];
    const int*   edge_dst     = (const int*)d_in[4];
    const int*   target_nodes = (const int*)d_in[5];
    const int*   pair_t       = (const int*)d_in[6];
    const int*   pair_s       = (const int*)d_in[7];
    const float* pair_mask    = (const float*)d_in[8];
    const float* W1t          = (const float*)d_in[9];
    const float* W2t          = (const float*)d_in[10];
    const float* W1c          = (const float*)d_in[11];
    const float* W2c          = (const float*)d_in[12];
    const float* Wpe          = (const float*)d_in[13];
    const float* z            = (const float*)d_in[14];
    const float* Wp1          = (const float*)d_in[15];
    const float* bp1          = (const float*)d_in[16];
    const float* Wp2          = (const float*)d_in[17];
    const float* bp2          = (const float*)d_in[18];
    float* out = (float*)d_out;

    float *buf1, *buf2, *tbuf;
    cudaGetSymbolAddress((void**)&buf1, g_buf1);
    cudaGetSymbolAddress((void**)&buf2, g_buf2);
    cudaGetSymbolAddress((void**)&tbuf, g_tbuf);

    cudaFuncSetAttribute(k_pred, cudaFuncAttributeMaxDynamicSharedMemorySize,
                         PRED_SMEM);

    const int TPB = 256;
    int gridN = (N_NODES + TPB - 1) / TPB;
    int gridE = (N_EDGES + TPB - 1) / TPB;
    int gridM = (N_NODES + 127) / 128;
    int gridA = (N_NODES + 7) / 8;

    // CSR build, big GEMM at launch slot 4 for the profiler window
    k_zero_cnt<<<gridN, TPB>>>();
    k_count<<<gridE, TPB>>>(edge_dst);
    k_scan<<<1, 1024>>>();
    k_gemm_tf32<<<gridM, 256>>>(x, W1t, buf2, N_NODES, 0);     // x @ W1t
    k_prep<<<gridN, TPB>>>();
    k_fill<<<gridE, TPB>>>(edge_src, edge_dst);
    k_flag<<<P_PAIRS / TPB, TPB>>>(pair_s, pair_mask);
    k_tflag<<<(T_NODES + TPB - 1) / TPB, TPB>>>(target_nodes);

    // tiny precomputes
    k_pe<<<gridN, TPB>>>(pos_enc, Wpe);
    k_zb<<<1, HP>>>(z, Wp1, bp1);
    k_wf<<<DIM, HP>>>(W2c, Wp1);

    // target GCN: h = relu(agg(xW1)) at tflag nodes only ; out_emb = agg(h)[targets] @ W2t
    k_agg_tflagged<<<gridA, 256>>>(buf2, buf1);
    k_agg_target<<<(T_NODES + 7) / 8, 256>>>(buf1, target_nodes, tbuf);
    k_gemm_tf32<<<T_NODES / 128, 256>>>(tbuf, W2t, out + (size_t)P_PAIRS * DOUT,
                                        T_NODES, 0);

    // context GCN: h_c = relu(agg(mxW1c)) ; m = agg(h_c) restricted to flagged nodes
    k_gemm_tf32<<<gridM, 256>>>(masked_x, W1c, buf2, N_NODES, 0);
    k_agg<<<gridA, 256>>>(buf2, buf1, 1);
    k_agg_flagged<<<gridA, 256>>>(buf1, buf2);   // m -> buf2

    // fused predictor MLP (64-row tiles, mask-tile skipping, k=32 weight chunks)
    k_pred<<<P_PAIRS / 64, 256, PRED_SMEM>>>(buf2, pair_s, pair_t, target_nodes,
                                             pair_mask, Wp1, Wp2, bp2, out);
}